// round 13
// baseline (speedup 1.0000x reference)
#include <cuda_runtime.h>
#include <cuda_fp16.h>
#include <math.h>
#include <stdint.h>

// ------------------------- problem dimensions -------------------------
#define L_SEQ   2048
#define E_DIM   4096
#define HR_DIM  1024
#define NH      32
#define D_ATT   32
#define NLAY    32
#define DD      16
#define OUT_FEAT (NLAY*NH*DD)   // 16384

// ------------------------- scratch (static device mem) ----------------
__device__ float g_attn[(size_t)L_SEQ*HR_DIM];
__device__ __half g_xh   [(size_t)L_SEQ*E_DIM];
__device__ __half g_hWi  [(size_t)HR_DIM*E_DIM];
__device__ __half g_hWq  [(size_t)HR_DIM*HR_DIM];
__device__ __half g_hWk  [(size_t)HR_DIM*HR_DIM];
__device__ __half g_hWv  [(size_t)HR_DIM*HR_DIM];
__device__ __half g_hWf1 [(size_t)2*HR_DIM*HR_DIM];
__device__ __half g_hWf2 [(size_t)E_DIM*2*HR_DIM];
__device__ __half g_hWqi1[(size_t)HR_DIM*E_DIM];
__device__ __half g_hWki1[(size_t)HR_DIM*E_DIM];
__device__ __half g_hWqi2[(size_t)OUT_FEAT*HR_DIM];
__device__ __half g_hWki2[(size_t)OUT_FEAT*HR_DIM];
__device__ __half g_hrh  [(size_t)L_SEQ*HR_DIM];
__device__ __half g_qh   [(size_t)L_SEQ*HR_DIM];
__device__ __half g_kh   [(size_t)L_SEQ*HR_DIM];
__device__ __half g_vh   [(size_t)L_SEQ*HR_DIM];
__device__ __half g_lnh  [(size_t)L_SEQ*HR_DIM];
__device__ __half g_f1h  [(size_t)L_SEQ*2*HR_DIM];
__device__ __half g_hidh [(size_t)L_SEQ*E_DIM];
__device__ __half g_aqh  [(size_t)L_SEQ*HR_DIM];
__device__ __half g_akh  [(size_t)L_SEQ*HR_DIM];

struct F16 { float f[16]; };
struct GArgs { const __half* A[3]; const __half* B[3]; void* C[3]; };
struct CvtArgs {
    const float4* src[11];
    uint2* dst[11];
    unsigned off[12];   // cumulative float4 counts
};

// ------------------------- helpers ------------------------------------
__device__ __forceinline__ float gelu_f(float x) {
    return 0.5f * x * (1.0f + erff(x * 0.7071067811865476f));
}
__device__ __forceinline__ float silu_f(float x) {
    return x / (1.0f + expf(-x));
}
__device__ __forceinline__ void mma16816(float c[4], const uint32_t a[4], const uint32_t b[2]) {
    asm volatile(
        "mma.sync.aligned.m16n8k16.row.col.f32.f16.f16.f32 "
        "{%0,%1,%2,%3}, {%4,%5,%6,%7}, {%8,%9}, {%0,%1,%2,%3};"
        : "+f"(c[0]), "+f"(c[1]), "+f"(c[2]), "+f"(c[3])
        : "r"(a[0]), "r"(a[1]), "r"(a[2]), "r"(a[3]), "r"(b[0]), "r"(b[1]));
}
__device__ __forceinline__ void cpa16(uint32_t saddr, const __half* g) {
    asm volatile("cp.async.cg.shared.global [%0], [%1], 16;\n" :: "r"(saddr), "l"(g));
}
#define CP_COMMIT() asm volatile("cp.async.commit_group;\n" ::: "memory")
#define CP_WAIT(n)  asm volatile("cp.async.wait_group %0;\n" :: "n"(n) : "memory")
__device__ __forceinline__ void ldsm4(uint32_t& r0, uint32_t& r1, uint32_t& r2, uint32_t& r3,
                                      uint32_t addr) {
    asm volatile("ldmatrix.sync.aligned.m8n8.x4.shared.b16 {%0,%1,%2,%3}, [%4];"
                 : "=r"(r0), "=r"(r1), "=r"(r2), "=r"(r3) : "r"(addr));
}
__device__ __forceinline__ void ldsm4t(uint32_t& r0, uint32_t& r1, uint32_t& r2, uint32_t& r3,
                                       uint32_t addr) {
    asm volatile("ldmatrix.sync.aligned.m8n8.x4.trans.shared.b16 {%0,%1,%2,%3}, [%4];"
                 : "=r"(r0), "=r"(r1), "=r"(r2), "=r"(r3) : "r"(addr));
}
__device__ __forceinline__ uint32_t packh2(float a, float b) {
    __half2 h = __floats2half2_rn(a, b);
    return *reinterpret_cast<uint32_t*>(&h);
}

// ------------------ batched convert: dst[s] = half(src[s]) ------------
__global__ __launch_bounds__(256)
void cvt_all(CvtArgs a)
{
    unsigned gid = blockIdx.x * 256u + threadIdx.x;
    if (gid >= a.off[11]) return;
    int s = 0;
#pragma unroll
    for (int i = 1; i < 11; i++) s += (gid >= a.off[i]) ? 1 : 0;
    unsigned idx = gid - a.off[s];
    float4 v = a.src[s][idx];
    uint2 o;
    o.x = packh2(v.x, v.y);
    o.y = packh2(v.z, v.w);
    a.dst[s][idx] = o;
}

// ---------------- FP16 GEMM: C[2048,N] = A[2048,K] * B[N,K]^T ---------
// CTA tile (MI*32)x128x32, 8 warps (2m x 4n), warp tile (MI*16)x32.
// MI=4: 128-row tile (round-10 proven); MI=2: 64-row tile (better fill).
// 2-stage cp.async.
// EPI: 0 none, 1 gelu(acc+bias), 2 acc+bias+resid, 3 silu(acc),
//      4 rope+permute into output (qi/ki), 5 qkv rope (z<2) fp16 out
// OUTH: 1 -> fp16 C, 0 -> fp32 C
template<int EPI, int OUTH, int MI>
__global__ __launch_bounds__(256, 2)
void tgemm(GArgs ga, const float* __restrict__ bias,
           const float* __restrict__ resid, int N, int K, F16 ft)
{
    constexpr int MROWS = MI * 32;
    constexpr int AIT = MI / 2;            // A-loader iterations (256 thr, 8-half chunks)
    __shared__ __align__(16) __half sA[2][MROWS*32];
    __shared__ __align__(16) __half sB[2][128*32];

    const __half* __restrict__ A = ga.A[blockIdx.z];
    const __half* __restrict__ B = ga.B[blockIdx.z];

    const int tid = threadIdx.x, wid = tid >> 5, lane = tid & 31;
    const int g = lane >> 2, tig = lane & 3;
    const int wm = (wid & 1) * (MI * 16);
    const int wn = (wid >> 1) * 32;
    const int bm = blockIdx.y * MROWS, bn = blockIdx.x * 128;

    uint32_t sA_u[2], sB_u[2];
    sA_u[0] = (uint32_t)__cvta_generic_to_shared(&sA[0][0]);
    sA_u[1] = (uint32_t)__cvta_generic_to_shared(&sA[1][0]);
    sB_u[0] = (uint32_t)__cvta_generic_to_shared(&sB[0][0]);
    sB_u[1] = (uint32_t)__cvta_generic_to_shared(&sB[1][0]);

    uint32_t aoff[AIT], boff[2];
    const __half* aptr[AIT];
    const __half* bptr[2];
#pragma unroll
    for (int i = 0; i < AIT; i++) {
        int id = tid + i * 256;
        int r = id >> 2, c = id & 3;
        aoff[i] = (uint32_t)(r * 64 + ((c ^ ((r >> 1) & 3)) << 4));
        aptr[i] = A + (size_t)(bm + r) * K + c * 8;
    }
#pragma unroll
    for (int i = 0; i < 2; i++) {
        int id = tid + i * 256;
        int r = id >> 2, c = id & 3;
        boff[i] = (uint32_t)(r * 64 + ((c ^ ((r >> 1) & 3)) << 4));
        bptr[i] = B + (size_t)(bn + r) * K + c * 8;
    }

    const int cAbit = lane >> 4;
    uint32_t aRowByte[MI]; int aMask[MI];
#pragma unroll
    for (int mi = 0; mi < MI; mi++) {
        int r = wm + mi * 16 + (lane & 15);
        aRowByte[mi] = (uint32_t)(r * 64);
        aMask[mi] = (r >> 1) & 3;
    }
    const int cBbit = (lane >> 3) & 1;
    uint32_t bRowByte[2]; int bMask[2];
#pragma unroll
    for (int p = 0; p < 2; p++) {
        int r = wn + p * 16 + ((lane >> 4) << 3) + (lane & 7);
        bRowByte[p] = (uint32_t)(r * 64);
        bMask[p] = (r >> 1) & 3;
    }

    float acc[MI][4][4];
#pragma unroll
    for (int mi = 0; mi < MI; mi++)
#pragma unroll
        for (int ni = 0; ni < 4; ni++)
#pragma unroll
            for (int c = 0; c < 4; c++) acc[mi][ni][c] = 0.0f;

#pragma unroll
    for (int i = 0; i < AIT; i++) { cpa16(sA_u[0] + aoff[i], aptr[i]); }
#pragma unroll
    for (int i = 0; i < 2; i++) { cpa16(sB_u[0] + boff[i], bptr[i]); }
    CP_COMMIT();
#pragma unroll
    for (int i = 0; i < AIT; i++) aptr[i] += 32;
#pragma unroll
    for (int i = 0; i < 2; i++) bptr[i] += 32;

    const int T = K >> 5;
    for (int t = 0; t < T; t++) {
        const int cur = t & 1, nxt = cur ^ 1;
        if (t + 1 < T) {
#pragma unroll
            for (int i = 0; i < AIT; i++) { cpa16(sA_u[nxt] + aoff[i], aptr[i]); }
#pragma unroll
            for (int i = 0; i < 2; i++) { cpa16(sB_u[nxt] + boff[i], bptr[i]); }
            CP_COMMIT();
#pragma unroll
            for (int i = 0; i < AIT; i++) aptr[i] += 32;
#pragma unroll
            for (int i = 0; i < 2; i++) bptr[i] += 32;
            CP_WAIT(1);
        } else {
            CP_WAIT(0);
        }
        __syncthreads();

        const uint32_t sAc = sA_u[cur], sBc = sB_u[cur];
#pragma unroll
        for (int kk = 0; kk < 2; kk++) {
            uint32_t af[MI][4], bf[4][2];
#pragma unroll
            for (int mi = 0; mi < MI; mi++)
                ldsm4(af[mi][0], af[mi][1], af[mi][2], af[mi][3],
                      sAc + aRowByte[mi] + (uint32_t)(((2*kk + cAbit) ^ aMask[mi]) << 4));
#pragma unroll
            for (int p = 0; p < 2; p++)
                ldsm4(bf[p*2][0], bf[p*2][1], bf[p*2+1][0], bf[p*2+1][1],
                      sBc + bRowByte[p] + (uint32_t)(((2*kk + cBbit) ^ bMask[p]) << 4));
#pragma unroll
            for (int mi = 0; mi < MI; mi++)
#pragma unroll
                for (int ni = 0; ni < 4; ni++)
                    mma16816(acc[mi][ni], af[mi], bf[ni]);
        }
        __syncthreads();
    }

    // ---------------- epilogue ----------------
    if (EPI == 4) {
        float* __restrict__ Cf = (float*)ga.C[blockIdx.z];
#pragma unroll
        for (int mi = 0; mi < MI; mi++) {
#pragma unroll
            for (int j = 0; j < 2; j++) {
                int nb = bn + wn + j * 16;
                int h  = (nb >> 4) & 31;
                int nl = nb >> 9;
                size_t ob0 = ((size_t)(nl * NH + h)) * L_SEQ;
                int i0 = tig * 2;
#pragma unroll
                for (int hf = 0; hf < 2; hf++) {
                    int l = bm + wm + mi * 16 + g + hf * 8;
                    size_t ob = (ob0 + l) * DD + i0;
                    float x1a = acc[mi][j*2  ][hf*2+0];
                    float x1b = acc[mi][j*2  ][hf*2+1];
                    float x2a = acc[mi][j*2+1][hf*2+0];
                    float x2b = acc[mi][j*2+1][hf*2+1];
                    float a0 = (float)l * ft.f[i0];
                    float a1 = (float)l * ft.f[i0+1];
                    float c0 = cosf(a0), s0 = sinf(a0);
                    float c1 = cosf(a1), s1 = sinf(a1);
                    *reinterpret_cast<float2*>(Cf + ob) =
                        make_float2(x1a*c0 - x2a*s0, x1b*c1 - x2b*s1);
                    *reinterpret_cast<float2*>(Cf + ob + 8) =
                        make_float2(x2a*c0 + x1a*s0, x2b*c1 + x1b*s1);
                }
            }
        }
        return;
    }
    if (EPI == 5) {
        __half* __restrict__ Ch = (__half*)ga.C[blockIdx.z];
        const bool dorope = (blockIdx.z < 2);
        const float sc = (blockIdx.z == 0) ? 0.17677669529663687f : 1.0f;
#pragma unroll
        for (int mi = 0; mi < MI; mi++) {
#pragma unroll
            for (int hf = 0; hf < 2; hf++) {
                int l = bm + wm + mi * 16 + g + hf * 8;
                size_t rowo = (size_t)l * N;
#pragma unroll
                for (int ni = 0; ni < 2; ni++) {
                    int i0 = ni * 8 + tig * 2;
                    int n0 = bn + wn + ni * 8 + tig * 2;
                    float x1a = acc[mi][ni  ][hf*2+0] * sc;
                    float x1b = acc[mi][ni  ][hf*2+1] * sc;
                    float x2a = acc[mi][ni+2][hf*2+0] * sc;
                    float x2b = acc[mi][ni+2][hf*2+1] * sc;
                    float y1a, y1b, y2a, y2b;
                    if (dorope) {
                        float a0 = (float)l * ft.f[i0];
                        float a1 = (float)l * ft.f[i0+1];
                        float c0 = cosf(a0), s0 = sinf(a0);
                        float c1 = cosf(a1), s1 = sinf(a1);
                        y1a = x1a*c0 - x2a*s0; y1b = x1b*c1 - x2b*s1;
                        y2a = x2a*c0 + x1a*s0; y2b = x2b*c1 + x1b*s1;
                    } else {
                        y1a = x1a; y1b = x1b; y2a = x2a; y2b = x2b;
                    }
                    *reinterpret_cast<uint32_t*>(Ch + rowo + n0)      = packh2(y1a, y1b);
                    *reinterpret_cast<uint32_t*>(Ch + rowo + n0 + 16) = packh2(y2a, y2b);
                }
            }
        }
        return;
    }

#pragma unroll
    for (int mi = 0; mi < MI; mi++) {
#pragma unroll
        for (int ni = 0; ni < 4; ni++) {
            int m0 = bm + wm + mi * 16 + g;
            int n0 = bn + wn + ni * 8 + tig * 2;
#pragma unroll
            for (int hf = 0; hf < 2; hf++) {
                int m = m0 + hf * 8;
                size_t off = (size_t)m * N + n0;
                float v0 = acc[mi][ni][hf * 2 + 0];
                float v1 = acc[mi][ni][hf * 2 + 1];
                if (EPI == 1) {
                    v0 = gelu_f(v0 + bias[n0]); v1 = gelu_f(v1 + bias[n0 + 1]);
                } else if (EPI == 2) {
                    v0 = v0 + bias[n0] + resid[off];
                    v1 = v1 + bias[n0 + 1] + resid[off + 1];
                } else if (EPI == 3) {
                    v0 = silu_f(v0); v1 = silu_f(v1);
                }
                if (OUTH) {
                    *reinterpret_cast<uint32_t*>((__half*)ga.C[blockIdx.z] + off) = packh2(v0, v1);
                } else {
                    *reinterpret_cast<float2*>((float*)ga.C[blockIdx.z] + off) =
                        make_float2(v0, v1);
                }
            }
        }
    }
}

// ---------------- tensor-core causal flash attention ------------------
// block = (64 queries, 1 head), 4 warps x 16 rows; K/V tiles of 64 keys.
__global__ __launch_bounds__(128)
void attn_mma(const __half* __restrict__ Q, const __half* __restrict__ K,
              const __half* __restrict__ V, float* __restrict__ O)
{
    __shared__ __align__(16) __half sQ[64*32];
    __shared__ __align__(16) __half sK[64*32];
    __shared__ __align__(16) __half sV[64*32];
    const int h = blockIdx.y;
    const int q0 = blockIdx.x * 64;
    const int tid = threadIdx.x, w = tid >> 5, lane = tid & 31;
    const int g = lane >> 2, tig = lane & 3;

    const uint32_t uQ = (uint32_t)__cvta_generic_to_shared(sQ);
    const uint32_t uK = (uint32_t)__cvta_generic_to_shared(sK);
    const uint32_t uV = (uint32_t)__cvta_generic_to_shared(sV);

#pragma unroll
    for (int i = 0; i < 2; i++) {
        int id = tid + i * 128;
        int r = id >> 2, c = id & 3;
        *reinterpret_cast<uint4*>(sQ + r * 32 + ((c ^ ((r >> 1) & 3)) << 3)) =
            *reinterpret_cast<const uint4*>(Q + (size_t)(q0 + r) * HR_DIM + h * 32 + c * 8);
    }

    const int cAbit = lane >> 4;
    const int aR = w * 16 + (lane & 15);
    const uint32_t aRowByte = (uint32_t)(aR * 64);
    const int aMask = (aR >> 1) & 3;
    const int cBbit = (lane >> 3) & 1;
    uint32_t bRowByte[4]; int bMask[4];
#pragma unroll
    for (int p = 0; p < 4; p++) {
        int r = p * 16 + ((lane >> 4) << 3) + (lane & 7);
        bRowByte[p] = (uint32_t)(r * 64);
        bMask[p] = (r >> 1) & 3;
    }
    const int vR0 = ((lane >> 3) & 1) * 8 + (lane & 7);
    const uint32_t vRowByte = (uint32_t)(vR0 * 64);
    const int vMask = (vR0 >> 1) & 3;
    const int vCbit = lane >> 4;

    float m0 = -INFINITY, m1 = -INFINITY, l0 = 0.0f, l1 = 0.0f;
    float Of[4][4];
#pragma unroll
    for (int nb = 0; nb < 4; nb++)
#pragma unroll
        for (int c = 0; c < 4; c++) Of[nb][c] = 0.0f;

    const int nt = q0 / 64 + 1;
    for (int tix = 0; tix < nt; tix++) {
        const int j0 = tix * 64;
#pragma unroll
        for (int i = 0; i < 2; i++) {
            int id = tid + i * 128;
            int r = id >> 2, c = id & 3;
            uint32_t so = r * 32 + ((c ^ ((r >> 1) & 3)) << 3);
            size_t go = (size_t)(j0 + r) * HR_DIM + h * 32 + c * 8;
            *reinterpret_cast<uint4*>(sK + so) = *reinterpret_cast<const uint4*>(K + go);
            *reinterpret_cast<uint4*>(sV + so) = *reinterpret_cast<const uint4*>(V + go);
        }
        __syncthreads();

        float Sf[8][4];
#pragma unroll
        for (int nb = 0; nb < 8; nb++)
#pragma unroll
            for (int c = 0; c < 4; c++) Sf[nb][c] = 0.0f;
#pragma unroll
        for (int kk = 0; kk < 2; kk++) {
            uint32_t af[4], bf[8][2];
            ldsm4(af[0], af[1], af[2], af[3],
                  uQ + aRowByte + (uint32_t)(((2*kk + cAbit) ^ aMask) << 4));
#pragma unroll
            for (int p = 0; p < 4; p++)
                ldsm4(bf[p*2][0], bf[p*2][1], bf[p*2+1][0], bf[p*2+1][1],
                      uK + bRowByte[p] + (uint32_t)(((2*kk + cBbit) ^ bMask[p]) << 4));
#pragma unroll
            for (int nb = 0; nb < 8; nb++)
                mma16816(Sf[nb], af, bf[nb]);
        }

        if (j0 == q0) {
            const int lr0 = q0 + w * 16 + g;
#pragma unroll
            for (int nb = 0; nb < 8; nb++) {
                int j = j0 + nb * 8 + tig * 2;
                if (j     > lr0    ) Sf[nb][0] = -1e30f;
                if (j + 1 > lr0    ) Sf[nb][1] = -1e30f;
                if (j     > lr0 + 8) Sf[nb][2] = -1e30f;
                if (j + 1 > lr0 + 8) Sf[nb][3] = -1e30f;
            }
        }

        float mx0 = -INFINITY, mx1 = -INFINITY;
#pragma unroll
        for (int nb = 0; nb < 8; nb++) {
            mx0 = fmaxf(mx0, fmaxf(Sf[nb][0], Sf[nb][1]));
            mx1 = fmaxf(mx1, fmaxf(Sf[nb][2], Sf[nb][3]));
        }
        mx0 = fmaxf(mx0, __shfl_xor_sync(0xffffffffu, mx0, 1));
        mx0 = fmaxf(mx0, __shfl_xor_sync(0xffffffffu, mx0, 2));
        mx1 = fmaxf(mx1, __shfl_xor_sync(0xffffffffu, mx1, 1));
        mx1 = fmaxf(mx1, __shfl_xor_sync(0xffffffffu, mx1, 2));
        float mn0 = fmaxf(m0, mx0), mn1 = fmaxf(m1, mx1);
        float al0 = __expf(m0 - mn0), al1 = __expf(m1 - mn1);
        float ps0 = 0.0f, ps1 = 0.0f;
#pragma unroll
        for (int nb = 0; nb < 8; nb++) {
            Sf[nb][0] = __expf(Sf[nb][0] - mn0);
            Sf[nb][1] = __expf(Sf[nb][1] - mn0);
            Sf[nb][2] = __expf(Sf[nb][2] - mn1);
            Sf[nb][3] = __expf(Sf[nb][3] - mn1);
            ps0 += Sf[nb][0] + Sf[nb][1];
            ps1 += Sf[nb][2] + Sf[nb][3];
        }
        ps0 += __shfl_xor_sync(0xffffffffu, ps0, 1);
        ps0 += __shfl_xor_sync(0xffffffffu, ps0, 2);
        ps1 += __shfl_xor_sync(0xffffffffu, ps1, 1);
        ps1 += __shfl_xor_sync(0xffffffffu, ps1, 2);
        l0 = l0 * al0 + ps0;
        l1 = l1 * al1 + ps1;
        m0 = mn0; m1 = mn1;
#pragma unroll
        for (int nb = 0; nb < 4; nb++) {
            Of[nb][0] *= al0; Of[nb][1] *= al0;
            Of[nb][2] *= al1; Of[nb][3] *= al1;
        }

#pragma unroll
        for (int kk = 0; kk < 4; kk++) {
            uint32_t pf[4];
            pf[0] = packh2(Sf[2*kk  ][0], Sf[2*kk  ][1]);
            pf[1] = packh2(Sf[2*kk  ][2], Sf[2*kk  ][3]);
            pf[2] = packh2(Sf[2*kk+1][0], Sf[2*kk+1][1]);
            pf[3] = packh2(Sf[2*kk+1][2], Sf[2*kk+1][3]);
#pragma unroll
            for (int p = 0; p < 2; p++) {
                uint32_t v0, v1, v2, v3;
                int dchunk = 2 * p + vCbit;
                ldsm4t(v0, v1, v2, v3,
                       uV + vRowByte + (uint32_t)(kk * 16 * 64)
                          + (uint32_t)((dchunk ^ vMask) << 4));
                uint32_t b0[2] = {v0, v1};
                uint32_t b1[2] = {v2, v3};
                mma16816(Of[p*2],   pf, b0);
                mma16816(Of[p*2+1], pf, b1);
            }
        }
        __syncthreads();
    }

    float inv0 = 1.0f / l0, inv1 = 1.0f / l1;
    const int lr = q0 + w * 16 + g;
#pragma unroll
    for (int nb = 0; nb < 4; nb++) {
        int d0 = nb * 8 + tig * 2;
        *reinterpret_cast<float2*>(O + (size_t)lr * HR_DIM + h * 32 + d0) =
            make_float2(Of[nb][0] * inv0, Of[nb][1] * inv0);
        *reinterpret_cast<float2*>(O + (size_t)(lr + 8) * HR_DIM + h * 32 + d0) =
            make_float2(Of[nb][2] * inv1, Of[nb][3] * inv1);
    }
}

// ------------------------- LayerNorm (rows of 1024, fp16 out) ---------
__global__ __launch_bounds__(256)
void layernorm_k(const float* __restrict__ in, const float* __restrict__ w,
                 const float* __restrict__ b, __half* __restrict__ out)
{
    __shared__ float red[8];
    const int row = blockIdx.x;
    const int tid = threadIdx.x;
    const int lane = tid & 31, wid = tid >> 5;
    float4 v = reinterpret_cast<const float4*>(in + (size_t)row * HR_DIM)[tid];

    float s = v.x + v.y + v.z + v.w;
#pragma unroll
    for (int o = 16; o; o >>= 1) s += __shfl_xor_sync(0xffffffffu, s, o);
    if (lane == 0) red[wid] = s;
    __syncthreads();
    float tot = red[0]+red[1]+red[2]+red[3]+red[4]+red[5]+red[6]+red[7];
    float mu = tot * (1.0f / HR_DIM);

    float dx0 = v.x - mu, dx1 = v.y - mu, dx2 = v.z - mu, dx3 = v.w - mu;
    float sq = dx0*dx0 + dx1*dx1 + dx2*dx2 + dx3*dx3;
#pragma unroll
    for (int o = 16; o; o >>= 1) sq += __shfl_xor_sync(0xffffffffu, sq, o);
    __syncthreads();
    if (lane == 0) red[wid] = sq;
    __syncthreads();
    float var = (red[0]+red[1]+red[2]+red[3]+red[4]+red[5]+red[6]+red[7]) * (1.0f / HR_DIM);
    float rstd = rsqrtf(var + 1e-5f);

    float4 wv = reinterpret_cast<const float4*>(w)[tid];
    float4 bv = reinterpret_cast<const float4*>(b)[tid];
    uint2 o;
    o.x = packh2(dx0 * rstd * wv.x + bv.x, dx1 * rstd * wv.y + bv.y);
    o.y = packh2(dx2 * rstd * wv.z + bv.z, dx3 * rstd * wv.w + bv.w);
    reinterpret_cast<uint2*>(out + (size_t)row * HR_DIM)[tid] = o;
}

// ------------------------- launcher -----------------------------------
extern "C" void kernel_launch(void* const* d_in, const int* in_sizes, int n_in,
                              void* d_out, int out_size)
{
    const float* x    = (const float*)d_in[0];
    const float* Wi   = (const float*)d_in[1];
    const float* Wq   = (const float*)d_in[2];
    const float* Wk   = (const float*)d_in[3];
    const float* Wv   = (const float*)d_in[4];
    const float* ln1w = (const float*)d_in[5];
    const float* ln1b = (const float*)d_in[6];
    const float* Wf1  = (const float*)d_in[7];
    const float* bf1  = (const float*)d_in[8];
    const float* Wf2  = (const float*)d_in[9];
    const float* bf2  = (const float*)d_in[10];
    const float* Wqi1 = (const float*)d_in[11];
    const float* Wqi2 = (const float*)d_in[12];
    const float* Wki1 = (const float*)d_in[13];
    const float* Wki2 = (const float*)d_in[14];
    float* out = (float*)d_out;

    float *attn;
    __half *xh,*hWi,*hWq,*hWk,*hWv,*hWf1,*hWf2,*hWqi1,*hWki1,*hWqi2,*hWki2;
    __half *hrh,*qh,*kh,*vh,*lnh,*f1h,*hidh,*aqh,*akh;
    cudaGetSymbolAddress((void**)&attn, g_attn);
    cudaGetSymbolAddress((void**)&xh,    g_xh);
    cudaGetSymbolAddress((void**)&hWi,   g_hWi);
    cudaGetSymbolAddress((void**)&hWq,   g_hWq);
    cudaGetSymbolAddress((void**)&hWk,   g_hWk);
    cudaGetSymbolAddress((void**)&hWv,   g_hWv);
    cudaGetSymbolAddress((void**)&hWf1,  g_hWf1);
    cudaGetSymbolAddress((void**)&hWf2,  g_hWf2);
    cudaGetSymbolAddress((void**)&hWqi1, g_hWqi1);
    cudaGetSymbolAddress((void**)&hWki1, g_hWki1);
    cudaGetSymbolAddress((void**)&hWqi2, g_hWqi2);
    cudaGetSymbolAddress((void**)&hWki2, g_hWki2);
    cudaGetSymbolAddress((void**)&hrh,   g_hrh);
    cudaGetSymbolAddress((void**)&qh,    g_qh);
    cudaGetSymbolAddress((void**)&kh,    g_kh);
    cudaGetSymbolAddress((void**)&vh,    g_vh);
    cudaGetSymbolAddress((void**)&lnh,   g_lnh);
    cudaGetSymbolAddress((void**)&f1h,   g_f1h);
    cudaGetSymbolAddress((void**)&hidh,  g_hidh);
    cudaGetSymbolAddress((void**)&aqh,   g_aqh);
    cudaGetSymbolAddress((void**)&akh,   g_akh);

    F16 t16; for (int i = 0; i < 16; i++) t16.f[i] = (float)(1.0 / pow(10000.0, (double)i / 16.0));
    F16 t8 = {}; for (int i = 0; i < 8; i++) t8.f[i] = (float)(1.0 / pow(10000.0, (double)i / 8.0));
    F16 t0 = {};

    // one batched fp32->fp16 convert over all 11 operands
    {
        CvtArgs ca;
        const float* srcs[11] = {x, Wi, Wq, Wk, Wv, Wf1, Wf2, Wqi1, Wki1, Wqi2, Wki2};
        __half* dsts[11] = {xh, hWi, hWq, hWk, hWv, hWf1, hWf2, hWqi1, hWki1, hWqi2, hWki2};
        size_t cnts[11] = {
            (size_t)L_SEQ*E_DIM, (size_t)HR_DIM*E_DIM,
            (size_t)HR_DIM*HR_DIM, (size_t)HR_DIM*HR_DIM, (size_t)HR_DIM*HR_DIM,
            (size_t)2*HR_DIM*HR_DIM, (size_t)E_DIM*2*HR_DIM,
            (size_t)HR_DIM*E_DIM, (size_t)HR_DIM*E_DIM,
            (size_t)OUT_FEAT*HR_DIM, (size_t)OUT_FEAT*HR_DIM
        };
        unsigned acc = 0;
        for (int i = 0; i < 11; i++) {
            ca.src[i] = (const float4*)srcs[i];
            ca.dst[i] = (uint2*)dsts[i];
            ca.off[i] = acc;
            acc += (unsigned)(cnts[i] / 4);
        }
        ca.off[11] = acc;
        cvt_all<<<(acc + 255) / 256, 256>>>(ca);
    }

    GArgs ga;

    // hr = x @ Wi^T  (fp16 out) -- 64-row tiles for better chip fill
    ga.A[0] = xh; ga.B[0] = hWi; ga.C[0] = hrh;
    tgemm<0,1,2><<<dim3(HR_DIM/128, 32, 1), 256>>>(ga, nullptr, nullptr, HR_DIM, E_DIM, t0);

    // q, k, v with fused rope (q scaled), fp16 out -- 64-row tiles
    ga.A[0] = hrh; ga.A[1] = hrh; ga.A[2] = hrh;
    ga.B[0] = hWq; ga.B[1] = hWk; ga.B[2] = hWv;
    ga.C[0] = qh;  ga.C[1] = kh;  ga.C[2] = vh;
    tgemm<5,1,2><<<dim3(HR_DIM/128, 32, 3), 256>>>(ga, nullptr, nullptr, HR_DIM, HR_DIM, t16);

    attn_mma<<<dim3(L_SEQ/64, NH), 128>>>(qh, kh, vh, attn);
    layernorm_k<<<L_SEQ, 256>>>(attn, ln1w, ln1b, lnh);

    // ffn1: gelu(ln @ Wf1^T + bf1) -> fp16 -- 64-row tiles
    ga.A[0] = lnh; ga.B[0] = hWf1; ga.C[0] = f1h;
    tgemm<1,1,2><<<dim3(2*HR_DIM/128, 32, 1), 256>>>(ga, bf1, nullptr, 2*HR_DIM, HR_DIM, t0);

    // ffn2 + residual -> fp16 -- 128-row tiles
    ga.A[0] = f1h; ga.B[0] = hWf2; ga.C[0] = hidh;
    tgemm<2,1,4><<<dim3(E_DIM/128, 16, 1), 256>>>(ga, bf2, x, E_DIM, 2*HR_DIM, t0);

    // silu projections -> fp16 -- 64-row tiles
    ga.A[0] = hidh; ga.A[1] = hidh;
    ga.B[0] = hWqi1; ga.B[1] = hWki1;
    ga.C[0] = aqh;  ga.C[1] = akh;
    tgemm<3,1,2><<<dim3(HR_DIM/128, 32, 2), 256>>>(ga, nullptr, nullptr, HR_DIM, E_DIM, t0);

    // importance projections with fused rope+permute into output -- 128-row
    ga.A[0] = aqh; ga.A[1] = akh;
    ga.B[0] = hWqi2; ga.B[1] = hWki2;
    ga.C[0] = out;  ga.C[1] = out + (size_t)NLAY*NH*L_SEQ*DD;
    tgemm<4,0,4><<<dim3(OUT_FEAT/128, 16, 2), 256>>>(ga, nullptr, nullptr, OUT_FEAT, HR_DIM, t8);
}

// round 14
// speedup vs baseline: 1.0452x; 1.0452x over previous
#include <cuda_runtime.h>
#include <cuda_fp16.h>
#include <math.h>
#include <stdint.h>

// ------------------------- problem dimensions -------------------------
#define L_SEQ   2048
#define E_DIM   4096
#define HR_DIM  1024
#define NH      32
#define D_ATT   32
#define NLAY    32
#define DD      16
#define OUT_FEAT (NLAY*NH*DD)   // 16384

// ------------------------- scratch (static device mem) ----------------
__device__ float g_attn[(size_t)L_SEQ*HR_DIM];
__device__ __half g_xh   [(size_t)L_SEQ*E_DIM];
__device__ __half g_hWi  [(size_t)HR_DIM*E_DIM];
__device__ __half g_hWq  [(size_t)HR_DIM*HR_DIM];
__device__ __half g_hWk  [(size_t)HR_DIM*HR_DIM];
__device__ __half g_hWv  [(size_t)HR_DIM*HR_DIM];
__device__ __half g_hWf1 [(size_t)2*HR_DIM*HR_DIM];
__device__ __half g_hWf2 [(size_t)E_DIM*2*HR_DIM];
__device__ __half g_hWqi1[(size_t)HR_DIM*E_DIM];
__device__ __half g_hWki1[(size_t)HR_DIM*E_DIM];
__device__ __half g_hWqi2[(size_t)OUT_FEAT*HR_DIM];
__device__ __half g_hWki2[(size_t)OUT_FEAT*HR_DIM];
__device__ __half g_hrh  [(size_t)L_SEQ*HR_DIM];
__device__ __half g_qh   [(size_t)L_SEQ*HR_DIM];
__device__ __half g_kh   [(size_t)L_SEQ*HR_DIM];
__device__ __half g_vh   [(size_t)L_SEQ*HR_DIM];
__device__ __half g_lnh  [(size_t)L_SEQ*HR_DIM];
__device__ __half g_f1h  [(size_t)L_SEQ*2*HR_DIM];
__device__ __half g_hidh [(size_t)L_SEQ*E_DIM];
__device__ __half g_aqh  [(size_t)L_SEQ*HR_DIM];
__device__ __half g_akh  [(size_t)L_SEQ*HR_DIM];

struct F16 { float f[16]; };
struct GArgs { const __half* A[3]; const __half* B[3]; void* C[3]; };
struct CvtArgs {
    const float4* src[11];
    uint2* dst[11];
    unsigned off[12];   // cumulative float4 counts
};

// ------------------------- helpers ------------------------------------
__device__ __forceinline__ float gelu_f(float x) {
    return 0.5f * x * (1.0f + erff(x * 0.7071067811865476f));
}
__device__ __forceinline__ float silu_f(float x) {
    return x / (1.0f + expf(-x));
}
__device__ __forceinline__ void mma16816(float c[4], const uint32_t a[4], const uint32_t b[2]) {
    asm volatile(
        "mma.sync.aligned.m16n8k16.row.col.f32.f16.f16.f32 "
        "{%0,%1,%2,%3}, {%4,%5,%6,%7}, {%8,%9}, {%0,%1,%2,%3};"
        : "+f"(c[0]), "+f"(c[1]), "+f"(c[2]), "+f"(c[3])
        : "r"(a[0]), "r"(a[1]), "r"(a[2]), "r"(a[3]), "r"(b[0]), "r"(b[1]));
}
__device__ __forceinline__ void cpa16(uint32_t saddr, const __half* g) {
    asm volatile("cp.async.cg.shared.global [%0], [%1], 16;\n" :: "r"(saddr), "l"(g));
}
#define CP_COMMIT() asm volatile("cp.async.commit_group;\n" ::: "memory")
#define CP_WAIT(n)  asm volatile("cp.async.wait_group %0;\n" :: "n"(n) : "memory")
__device__ __forceinline__ void ldsm4(uint32_t& r0, uint32_t& r1, uint32_t& r2, uint32_t& r3,
                                      uint32_t addr) {
    asm volatile("ldmatrix.sync.aligned.m8n8.x4.shared.b16 {%0,%1,%2,%3}, [%4];"
                 : "=r"(r0), "=r"(r1), "=r"(r2), "=r"(r3) : "r"(addr));
}
__device__ __forceinline__ void ldsm4t(uint32_t& r0, uint32_t& r1, uint32_t& r2, uint32_t& r3,
                                       uint32_t addr) {
    asm volatile("ldmatrix.sync.aligned.m8n8.x4.trans.shared.b16 {%0,%1,%2,%3}, [%4];"
                 : "=r"(r0), "=r"(r1), "=r"(r2), "=r"(r3) : "r"(addr));
}
__device__ __forceinline__ uint32_t packh2(float a, float b) {
    __half2 h = __floats2half2_rn(a, b);
    return *reinterpret_cast<uint32_t*>(&h);
}

// ------------------ batched convert: dst[s] = half(src[s]) ------------
__global__ __launch_bounds__(256)
void cvt_all(CvtArgs a)
{
    unsigned gid = blockIdx.x * 256u + threadIdx.x;
    if (gid >= a.off[11]) return;
    int s = 0;
#pragma unroll
    for (int i = 1; i < 11; i++) s += (gid >= a.off[i]) ? 1 : 0;
    unsigned idx = gid - a.off[s];
    float4 v = a.src[s][idx];
    uint2 o;
    o.x = packh2(v.x, v.y);
    o.y = packh2(v.z, v.w);
    a.dst[s][idx] = o;
}

// ---------------- FP16 GEMM: C[2048,N] = A[2048,K] * B[N,K]^T ---------
// CTA tile (MI*32)x128x32, 8 warps (2m x 4n), warp tile (MI*16)x32.
// MI=4 everywhere (round-12 proven config). 2-stage cp.async.
// EPI: 0 none, 1 gelu(acc+bias), 2 acc+bias+resid, 3 silu(acc),
//      4 rope+permute into output (qi/ki), 5 qkv rope (z<2) fp16 out
// OUTH: 1 -> fp16 C, 0 -> fp32 C
template<int EPI, int OUTH, int MI>
__global__ __launch_bounds__(256, 2)
void tgemm(GArgs ga, const float* __restrict__ bias,
           const float* __restrict__ resid, int N, int K, F16 ft)
{
    constexpr int MROWS = MI * 32;
    constexpr int AIT = MI / 2;
    __shared__ __align__(16) __half sA[2][MROWS*32];
    __shared__ __align__(16) __half sB[2][128*32];

    const __half* __restrict__ A = ga.A[blockIdx.z];
    const __half* __restrict__ B = ga.B[blockIdx.z];

    const int tid = threadIdx.x, wid = tid >> 5, lane = tid & 31;
    const int g = lane >> 2, tig = lane & 3;
    const int wm = (wid & 1) * (MI * 16);
    const int wn = (wid >> 1) * 32;
    const int bm = blockIdx.y * MROWS, bn = blockIdx.x * 128;

    uint32_t sA_u[2], sB_u[2];
    sA_u[0] = (uint32_t)__cvta_generic_to_shared(&sA[0][0]);
    sA_u[1] = (uint32_t)__cvta_generic_to_shared(&sA[1][0]);
    sB_u[0] = (uint32_t)__cvta_generic_to_shared(&sB[0][0]);
    sB_u[1] = (uint32_t)__cvta_generic_to_shared(&sB[1][0]);

    uint32_t aoff[AIT], boff[2];
    const __half* aptr[AIT];
    const __half* bptr[2];
#pragma unroll
    for (int i = 0; i < AIT; i++) {
        int id = tid + i * 256;
        int r = id >> 2, c = id & 3;
        aoff[i] = (uint32_t)(r * 64 + ((c ^ ((r >> 1) & 3)) << 4));
        aptr[i] = A + (size_t)(bm + r) * K + c * 8;
    }
#pragma unroll
    for (int i = 0; i < 2; i++) {
        int id = tid + i * 256;
        int r = id >> 2, c = id & 3;
        boff[i] = (uint32_t)(r * 64 + ((c ^ ((r >> 1) & 3)) << 4));
        bptr[i] = B + (size_t)(bn + r) * K + c * 8;
    }

    const int cAbit = lane >> 4;
    uint32_t aRowByte[MI]; int aMask[MI];
#pragma unroll
    for (int mi = 0; mi < MI; mi++) {
        int r = wm + mi * 16 + (lane & 15);
        aRowByte[mi] = (uint32_t)(r * 64);
        aMask[mi] = (r >> 1) & 3;
    }
    const int cBbit = (lane >> 3) & 1;
    uint32_t bRowByte[2]; int bMask[2];
#pragma unroll
    for (int p = 0; p < 2; p++) {
        int r = wn + p * 16 + ((lane >> 4) << 3) + (lane & 7);
        bRowByte[p] = (uint32_t)(r * 64);
        bMask[p] = (r >> 1) & 3;
    }

    float acc[MI][4][4];
#pragma unroll
    for (int mi = 0; mi < MI; mi++)
#pragma unroll
        for (int ni = 0; ni < 4; ni++)
#pragma unroll
            for (int c = 0; c < 4; c++) acc[mi][ni][c] = 0.0f;

#pragma unroll
    for (int i = 0; i < AIT; i++) { cpa16(sA_u[0] + aoff[i], aptr[i]); }
#pragma unroll
    for (int i = 0; i < 2; i++) { cpa16(sB_u[0] + boff[i], bptr[i]); }
    CP_COMMIT();
#pragma unroll
    for (int i = 0; i < AIT; i++) aptr[i] += 32;
#pragma unroll
    for (int i = 0; i < 2; i++) bptr[i] += 32;

    const int T = K >> 5;
    for (int t = 0; t < T; t++) {
        const int cur = t & 1, nxt = cur ^ 1;
        if (t + 1 < T) {
#pragma unroll
            for (int i = 0; i < AIT; i++) { cpa16(sA_u[nxt] + aoff[i], aptr[i]); }
#pragma unroll
            for (int i = 0; i < 2; i++) { cpa16(sB_u[nxt] + boff[i], bptr[i]); }
            CP_COMMIT();
#pragma unroll
            for (int i = 0; i < AIT; i++) aptr[i] += 32;
#pragma unroll
            for (int i = 0; i < 2; i++) bptr[i] += 32;
            CP_WAIT(1);
        } else {
            CP_WAIT(0);
        }
        __syncthreads();

        const uint32_t sAc = sA_u[cur], sBc = sB_u[cur];
#pragma unroll
        for (int kk = 0; kk < 2; kk++) {
            uint32_t af[MI][4], bf[4][2];
#pragma unroll
            for (int mi = 0; mi < MI; mi++)
                ldsm4(af[mi][0], af[mi][1], af[mi][2], af[mi][3],
                      sAc + aRowByte[mi] + (uint32_t)(((2*kk + cAbit) ^ aMask[mi]) << 4));
#pragma unroll
            for (int p = 0; p < 2; p++)
                ldsm4(bf[p*2][0], bf[p*2][1], bf[p*2+1][0], bf[p*2+1][1],
                      sBc + bRowByte[p] + (uint32_t)(((2*kk + cBbit) ^ bMask[p]) << 4));
#pragma unroll
            for (int mi = 0; mi < MI; mi++)
#pragma unroll
                for (int ni = 0; ni < 4; ni++)
                    mma16816(acc[mi][ni], af[mi], bf[ni]);
        }
        __syncthreads();
    }

    // ---------------- epilogue ----------------
    if (EPI == 4) {
        float* __restrict__ Cf = (float*)ga.C[blockIdx.z];
#pragma unroll
        for (int mi = 0; mi < MI; mi++) {
#pragma unroll
            for (int j = 0; j < 2; j++) {
                int nb = bn + wn + j * 16;
                int h  = (nb >> 4) & 31;
                int nl = nb >> 9;
                size_t ob0 = ((size_t)(nl * NH + h)) * L_SEQ;
                int i0 = tig * 2;
#pragma unroll
                for (int hf = 0; hf < 2; hf++) {
                    int l = bm + wm + mi * 16 + g + hf * 8;
                    size_t ob = (ob0 + l) * DD + i0;
                    float x1a = acc[mi][j*2  ][hf*2+0];
                    float x1b = acc[mi][j*2  ][hf*2+1];
                    float x2a = acc[mi][j*2+1][hf*2+0];
                    float x2b = acc[mi][j*2+1][hf*2+1];
                    float a0 = (float)l * ft.f[i0];
                    float a1 = (float)l * ft.f[i0+1];
                    float c0 = cosf(a0), s0 = sinf(a0);
                    float c1 = cosf(a1), s1 = sinf(a1);
                    *reinterpret_cast<float2*>(Cf + ob) =
                        make_float2(x1a*c0 - x2a*s0, x1b*c1 - x2b*s1);
                    *reinterpret_cast<float2*>(Cf + ob + 8) =
                        make_float2(x2a*c0 + x1a*s0, x2b*c1 + x1b*s1);
                }
            }
        }
        return;
    }
    if (EPI == 5) {
        __half* __restrict__ Ch = (__half*)ga.C[blockIdx.z];
        const bool dorope = (blockIdx.z < 2);
        const float sc = (blockIdx.z == 0) ? 0.17677669529663687f : 1.0f;
#pragma unroll
        for (int mi = 0; mi < MI; mi++) {
#pragma unroll
            for (int hf = 0; hf < 2; hf++) {
                int l = bm + wm + mi * 16 + g + hf * 8;
                size_t rowo = (size_t)l * N;
#pragma unroll
                for (int ni = 0; ni < 2; ni++) {
                    int i0 = ni * 8 + tig * 2;
                    int n0 = bn + wn + ni * 8 + tig * 2;
                    float x1a = acc[mi][ni  ][hf*2+0] * sc;
                    float x1b = acc[mi][ni  ][hf*2+1] * sc;
                    float x2a = acc[mi][ni+2][hf*2+0] * sc;
                    float x2b = acc[mi][ni+2][hf*2+1] * sc;
                    float y1a, y1b, y2a, y2b;
                    if (dorope) {
                        float a0 = (float)l * ft.f[i0];
                        float a1 = (float)l * ft.f[i0+1];
                        float c0 = cosf(a0), s0 = sinf(a0);
                        float c1 = cosf(a1), s1 = sinf(a1);
                        y1a = x1a*c0 - x2a*s0; y1b = x1b*c1 - x2b*s1;
                        y2a = x2a*c0 + x1a*s0; y2b = x2b*c1 + x1b*s1;
                    } else {
                        y1a = x1a; y1b = x1b; y2a = x2a; y2b = x2b;
                    }
                    *reinterpret_cast<uint32_t*>(Ch + rowo + n0)      = packh2(y1a, y1b);
                    *reinterpret_cast<uint32_t*>(Ch + rowo + n0 + 16) = packh2(y2a, y2b);
                }
            }
        }
        return;
    }

#pragma unroll
    for (int mi = 0; mi < MI; mi++) {
#pragma unroll
        for (int ni = 0; ni < 4; ni++) {
            int m0 = bm + wm + mi * 16 + g;
            int n0 = bn + wn + ni * 8 + tig * 2;
#pragma unroll
            for (int hf = 0; hf < 2; hf++) {
                int m = m0 + hf * 8;
                size_t off = (size_t)m * N + n0;
                float v0 = acc[mi][ni][hf * 2 + 0];
                float v1 = acc[mi][ni][hf * 2 + 1];
                if (EPI == 1) {
                    v0 = gelu_f(v0 + bias[n0]); v1 = gelu_f(v1 + bias[n0 + 1]);
                } else if (EPI == 2) {
                    v0 = v0 + bias[n0] + resid[off];
                    v1 = v1 + bias[n0 + 1] + resid[off + 1];
                } else if (EPI == 3) {
                    v0 = silu_f(v0); v1 = silu_f(v1);
                }
                if (OUTH) {
                    *reinterpret_cast<uint32_t*>((__half*)ga.C[blockIdx.z] + off) = packh2(v0, v1);
                } else {
                    *reinterpret_cast<float2*>((float*)ga.C[blockIdx.z] + off) =
                        make_float2(v0, v1);
                }
            }
        }
    }
}

// ---------------- tensor-core causal flash attention ------------------
// block = (128 queries = 2 tiles of 64, 1 head), 4 warps; K/V tiles of 64
// keys shared across both q-tiles.
__global__ __launch_bounds__(128)
void attn_mma(const __half* __restrict__ Q, const __half* __restrict__ K,
              const __half* __restrict__ V, float* __restrict__ O)
{
    __shared__ __align__(16) __half sQ[128*32];
    __shared__ __align__(16) __half sK[64*32];
    __shared__ __align__(16) __half sV[64*32];
    const int h = blockIdx.y;
    const int q0 = blockIdx.x * 128;
    const int tid = threadIdx.x, w = tid >> 5, lane = tid & 31;
    const int g = lane >> 2, tig = lane & 3;

    const uint32_t uQ = (uint32_t)__cvta_generic_to_shared(sQ);
    const uint32_t uK = (uint32_t)__cvta_generic_to_shared(sK);
    const uint32_t uV = (uint32_t)__cvta_generic_to_shared(sV);

    // load both Q tiles (128 rows x 32 halves, swizzled 16B chunks)
#pragma unroll
    for (int i = 0; i < 4; i++) {
        int id = tid + i * 128;
        int r = id >> 2, c = id & 3;
        *reinterpret_cast<uint4*>(sQ + r * 32 + ((c ^ ((r >> 1) & 3)) << 3)) =
            *reinterpret_cast<const uint4*>(Q + (size_t)(q0 + r) * HR_DIM + h * 32 + c * 8);
    }

    // fragment addressing
    const int cAbit = lane >> 4;
    uint32_t aRowByte[2]; int aMask[2];
#pragma unroll
    for (int tau = 0; tau < 2; tau++) {
        int r = tau * 64 + w * 16 + (lane & 15);
        aRowByte[tau] = (uint32_t)(r * 64);
        aMask[tau] = (r >> 1) & 3;
    }
    const int cBbit = (lane >> 3) & 1;
    uint32_t bRowByte[4]; int bMask[4];
#pragma unroll
    for (int p = 0; p < 4; p++) {
        int r = p * 16 + ((lane >> 4) << 3) + (lane & 7);
        bRowByte[p] = (uint32_t)(r * 64);
        bMask[p] = (r >> 1) & 3;
    }
    const int vR0 = ((lane >> 3) & 1) * 8 + (lane & 7);
    const uint32_t vRowByte = (uint32_t)(vR0 * 64);
    const int vMask = (vR0 >> 1) & 3;
    const int vCbit = lane >> 4;

    float m0[2], m1[2], l0[2], l1[2], Of[2][4][4];
#pragma unroll
    for (int tau = 0; tau < 2; tau++) {
        m0[tau] = -INFINITY; m1[tau] = -INFINITY; l0[tau] = 0.0f; l1[tau] = 0.0f;
#pragma unroll
        for (int nb = 0; nb < 4; nb++)
#pragma unroll
            for (int c = 0; c < 4; c++) Of[tau][nb][c] = 0.0f;
    }

    const int nt = blockIdx.x * 2 + 2;     // K/V tiles needed
    for (int tix = 0; tix < nt; tix++) {
        const int j0 = tix * 64;
        // load K,V tiles (16B chunks)
#pragma unroll
        for (int i = 0; i < 2; i++) {
            int id = tid + i * 128;
            int r = id >> 2, c = id & 3;
            uint32_t so = r * 32 + ((c ^ ((r >> 1) & 3)) << 3);
            size_t go = (size_t)(j0 + r) * HR_DIM + h * 32 + c * 8;
            *reinterpret_cast<uint4*>(sK + so) = *reinterpret_cast<const uint4*>(K + go);
            *reinterpret_cast<uint4*>(sV + so) = *reinterpret_cast<const uint4*>(V + go);
        }
        __syncthreads();

#pragma unroll
        for (int tau = 0; tau < 2; tau++) {
            const int diag = blockIdx.x * 2 + tau;
            if (tix > diag) continue;

            // S = Q_tau @ K^T  (16 rows x 64 keys per warp)
            float Sf[8][4];
#pragma unroll
            for (int nb = 0; nb < 8; nb++)
#pragma unroll
                for (int c = 0; c < 4; c++) Sf[nb][c] = 0.0f;
#pragma unroll
            for (int kk = 0; kk < 2; kk++) {
                uint32_t af[4], bf[8][2];
                ldsm4(af[0], af[1], af[2], af[3],
                      uQ + aRowByte[tau] + (uint32_t)(((2*kk + cAbit) ^ aMask[tau]) << 4));
#pragma unroll
                for (int p = 0; p < 4; p++)
                    ldsm4(bf[p*2][0], bf[p*2][1], bf[p*2+1][0], bf[p*2+1][1],
                          uK + bRowByte[p] + (uint32_t)(((2*kk + cBbit) ^ bMask[p]) << 4));
#pragma unroll
                for (int nb = 0; nb < 8; nb++)
                    mma16816(Sf[nb], af, bf[nb]);
            }

            // causal mask on the diagonal tile
            if (tix == diag) {
                const int lr0 = q0 + tau * 64 + w * 16 + g;
#pragma unroll
                for (int nb = 0; nb < 8; nb++) {
                    int j = j0 + nb * 8 + tig * 2;
                    if (j     > lr0    ) Sf[nb][0] = -1e30f;
                    if (j + 1 > lr0    ) Sf[nb][1] = -1e30f;
                    if (j     > lr0 + 8) Sf[nb][2] = -1e30f;
                    if (j + 1 > lr0 + 8) Sf[nb][3] = -1e30f;
                }
            }

            // online softmax (rows g and g+8)
            float mx0 = -INFINITY, mx1 = -INFINITY;
#pragma unroll
            for (int nb = 0; nb < 8; nb++) {
                mx0 = fmaxf(mx0, fmaxf(Sf[nb][0], Sf[nb][1]));
                mx1 = fmaxf(mx1, fmaxf(Sf[nb][2], Sf[nb][3]));
            }
            mx0 = fmaxf(mx0, __shfl_xor_sync(0xffffffffu, mx0, 1));
            mx0 = fmaxf(mx0, __shfl_xor_sync(0xffffffffu, mx0, 2));
            mx1 = fmaxf(mx1, __shfl_xor_sync(0xffffffffu, mx1, 1));
            mx1 = fmaxf(mx1, __shfl_xor_sync(0xffffffffu, mx1, 2));
            float mn0 = fmaxf(m0[tau], mx0), mn1 = fmaxf(m1[tau], mx1);
            float al0 = __expf(m0[tau] - mn0), al1 = __expf(m1[tau] - mn1);
            float ps0 = 0.0f, ps1 = 0.0f;
#pragma unroll
            for (int nb = 0; nb < 8; nb++) {
                Sf[nb][0] = __expf(Sf[nb][0] - mn0);
                Sf[nb][1] = __expf(Sf[nb][1] - mn0);
                Sf[nb][2] = __expf(Sf[nb][2] - mn1);
                Sf[nb][3] = __expf(Sf[nb][3] - mn1);
                ps0 += Sf[nb][0] + Sf[nb][1];
                ps1 += Sf[nb][2] + Sf[nb][3];
            }
            ps0 += __shfl_xor_sync(0xffffffffu, ps0, 1);
            ps0 += __shfl_xor_sync(0xffffffffu, ps0, 2);
            ps1 += __shfl_xor_sync(0xffffffffu, ps1, 1);
            ps1 += __shfl_xor_sync(0xffffffffu, ps1, 2);
            l0[tau] = l0[tau] * al0 + ps0;
            l1[tau] = l1[tau] * al1 + ps1;
            m0[tau] = mn0; m1[tau] = mn1;
#pragma unroll
            for (int nb = 0; nb < 4; nb++) {
                Of[tau][nb][0] *= al0; Of[tau][nb][1] *= al0;
                Of[tau][nb][2] *= al1; Of[tau][nb][3] *= al1;
            }

            // P (fp16) @ V
#pragma unroll
            for (int kk = 0; kk < 4; kk++) {
                uint32_t pf[4];
                pf[0] = packh2(Sf[2*kk  ][0], Sf[2*kk  ][1]);
                pf[1] = packh2(Sf[2*kk  ][2], Sf[2*kk  ][3]);
                pf[2] = packh2(Sf[2*kk+1][0], Sf[2*kk+1][1]);
                pf[3] = packh2(Sf[2*kk+1][2], Sf[2*kk+1][3]);
#pragma unroll
                for (int p = 0; p < 2; p++) {
                    uint32_t v0, v1, v2, v3;
                    int dchunk = 2 * p + vCbit;
                    ldsm4t(v0, v1, v2, v3,
                           uV + vRowByte + (uint32_t)(kk * 16 * 64)
                              + (uint32_t)((dchunk ^ vMask) << 4));
                    uint32_t b0[2] = {v0, v1};
                    uint32_t b1[2] = {v2, v3};
                    mma16816(Of[tau][p*2],   pf, b0);
                    mma16816(Of[tau][p*2+1], pf, b1);
                }
            }
        }
        __syncthreads();
    }

    // write O = Of / l
#pragma unroll
    for (int tau = 0; tau < 2; tau++) {
        float inv0 = 1.0f / l0[tau], inv1 = 1.0f / l1[tau];
        const int lr = q0 + tau * 64 + w * 16 + g;
#pragma unroll
        for (int nb = 0; nb < 4; nb++) {
            int d0 = nb * 8 + tig * 2;
            *reinterpret_cast<float2*>(O + (size_t)lr * HR_DIM + h * 32 + d0) =
                make_float2(Of[tau][nb][0] * inv0, Of[tau][nb][1] * inv0);
            *reinterpret_cast<float2*>(O + (size_t)(lr + 8) * HR_DIM + h * 32 + d0) =
                make_float2(Of[tau][nb][2] * inv1, Of[tau][nb][3] * inv1);
        }
    }
}

// ------------------------- LayerNorm (rows of 1024, fp16 out) ---------
__global__ __launch_bounds__(256)
void layernorm_k(const float* __restrict__ in, const float* __restrict__ w,
                 const float* __restrict__ b, __half* __restrict__ out)
{
    __shared__ float red[8];
    const int row = blockIdx.x;
    const int tid = threadIdx.x;
    const int lane = tid & 31, wid = tid >> 5;
    float4 v = reinterpret_cast<const float4*>(in + (size_t)row * HR_DIM)[tid];

    float s = v.x + v.y + v.z + v.w;
#pragma unroll
    for (int o = 16; o; o >>= 1) s += __shfl_xor_sync(0xffffffffu, s, o);
    if (lane == 0) red[wid] = s;
    __syncthreads();
    float tot = red[0]+red[1]+red[2]+red[3]+red[4]+red[5]+red[6]+red[7];
    float mu = tot * (1.0f / HR_DIM);

    float dx0 = v.x - mu, dx1 = v.y - mu, dx2 = v.z - mu, dx3 = v.w - mu;
    float sq = dx0*dx0 + dx1*dx1 + dx2*dx2 + dx3*dx3;
#pragma unroll
    for (int o = 16; o; o >>= 1) sq += __shfl_xor_sync(0xffffffffu, sq, o);
    __syncthreads();
    if (lane == 0) red[wid] = sq;
    __syncthreads();
    float var = (red[0]+red[1]+red[2]+red[3]+red[4]+red[5]+red[6]+red[7]) * (1.0f / HR_DIM);
    float rstd = rsqrtf(var + 1e-5f);

    float4 wv = reinterpret_cast<const float4*>(w)[tid];
    float4 bv = reinterpret_cast<const float4*>(b)[tid];
    uint2 o;
    o.x = packh2(dx0 * rstd * wv.x + bv.x, dx1 * rstd * wv.y + bv.y);
    o.y = packh2(dx2 * rstd * wv.z + bv.z, dx3 * rstd * wv.w + bv.w);
    reinterpret_cast<uint2*>(out + (size_t)row * HR_DIM)[tid] = o;
}

// ------------------------- launcher -----------------------------------
extern "C" void kernel_launch(void* const* d_in, const int* in_sizes, int n_in,
                              void* d_out, int out_size)
{
    const float* x    = (const float*)d_in[0];
    const float* Wi   = (const float*)d_in[1];
    const float* Wq   = (const float*)d_in[2];
    const float* Wk   = (const float*)d_in[3];
    const float* Wv   = (const float*)d_in[4];
    const float* ln1w = (const float*)d_in[5];
    const float* ln1b = (const float*)d_in[6];
    const float* Wf1  = (const float*)d_in[7];
    const float* bf1  = (const float*)d_in[8];
    const float* Wf2  = (const float*)d_in[9];
    const float* bf2  = (const float*)d_in[10];
    const float* Wqi1 = (const float*)d_in[11];
    const float* Wqi2 = (const float*)d_in[12];
    const float* Wki1 = (const float*)d_in[13];
    const float* Wki2 = (const float*)d_in[14];
    float* out = (float*)d_out;

    float *attn;
    __half *xh,*hWi,*hWq,*hWk,*hWv,*hWf1,*hWf2,*hWqi1,*hWki1,*hWqi2,*hWki2;
    __half *hrh,*qh,*kh,*vh,*lnh,*f1h,*hidh,*aqh,*akh;
    cudaGetSymbolAddress((void**)&attn, g_attn);
    cudaGetSymbolAddress((void**)&xh,    g_xh);
    cudaGetSymbolAddress((void**)&hWi,   g_hWi);
    cudaGetSymbolAddress((void**)&hWq,   g_hWq);
    cudaGetSymbolAddress((void**)&hWk,   g_hWk);
    cudaGetSymbolAddress((void**)&hWv,   g_hWv);
    cudaGetSymbolAddress((void**)&hWf1,  g_hWf1);
    cudaGetSymbolAddress((void**)&hWf2,  g_hWf2);
    cudaGetSymbolAddress((void**)&hWqi1, g_hWqi1);
    cudaGetSymbolAddress((void**)&hWki1, g_hWki1);
    cudaGetSymbolAddress((void**)&hWqi2, g_hWqi2);
    cudaGetSymbolAddress((void**)&hWki2, g_hWki2);
    cudaGetSymbolAddress((void**)&hrh,   g_hrh);
    cudaGetSymbolAddress((void**)&qh,    g_qh);
    cudaGetSymbolAddress((void**)&kh,    g_kh);
    cudaGetSymbolAddress((void**)&vh,    g_vh);
    cudaGetSymbolAddress((void**)&lnh,   g_lnh);
    cudaGetSymbolAddress((void**)&f1h,   g_f1h);
    cudaGetSymbolAddress((void**)&hidh,  g_hidh);
    cudaGetSymbolAddress((void**)&aqh,   g_aqh);
    cudaGetSymbolAddress((void**)&akh,   g_akh);

    F16 t16; for (int i = 0; i < 16; i++) t16.f[i] = (float)(1.0 / pow(10000.0, (double)i / 16.0));
    F16 t8 = {}; for (int i = 0; i < 8; i++) t8.f[i] = (float)(1.0 / pow(10000.0, (double)i / 8.0));
    F16 t0 = {};

    // one batched fp32->fp16 convert over all 11 operands
    {
        CvtArgs ca;
        const float* srcs[11] = {x, Wi, Wq, Wk, Wv, Wf1, Wf2, Wqi1, Wki1, Wqi2, Wki2};
        __half* dsts[11] = {xh, hWi, hWq, hWk, hWv, hWf1, hWf2, hWqi1, hWki1, hWqi2, hWki2};
        size_t cnts[11] = {
            (size_t)L_SEQ*E_DIM, (size_t)HR_DIM*E_DIM,
            (size_t)HR_DIM*HR_DIM, (size_t)HR_DIM*HR_DIM, (size_t)HR_DIM*HR_DIM,
            (size_t)2*HR_DIM*HR_DIM, (size_t)E_DIM*2*HR_DIM,
            (size_t)HR_DIM*E_DIM, (size_t)HR_DIM*E_DIM,
            (size_t)OUT_FEAT*HR_DIM, (size_t)OUT_FEAT*HR_DIM
        };
        unsigned acc = 0;
        for (int i = 0; i < 11; i++) {
            ca.src[i] = (const float4*)srcs[i];
            ca.dst[i] = (uint2*)dsts[i];
            ca.off[i] = acc;
            acc += (unsigned)(cnts[i] / 4);
        }
        ca.off[11] = acc;
        cvt_all<<<(acc + 255) / 256, 256>>>(ca);
    }

    GArgs ga;

    // hr = x @ Wi^T  (fp16 out)
    ga.A[0] = xh; ga.B[0] = hWi; ga.C[0] = hrh;
    tgemm<0,1,4><<<dim3(HR_DIM/128, 16, 1), 256>>>(ga, nullptr, nullptr, HR_DIM, E_DIM, t0);

    // q, k, v with fused rope (q scaled), fp16 out
    ga.A[0] = hrh; ga.A[1] = hrh; ga.A[2] = hrh;
    ga.B[0] = hWq; ga.B[1] = hWk; ga.B[2] = hWv;
    ga.C[0] = qh;  ga.C[1] = kh;  ga.C[2] = vh;
    tgemm<5,1,4><<<dim3(HR_DIM/128, 16, 3), 256>>>(ga, nullptr, nullptr, HR_DIM, HR_DIM, t16);

    attn_mma<<<dim3(L_SEQ/128, NH), 128>>>(qh, kh, vh, attn);
    layernorm_k<<<L_SEQ, 256>>>(attn, ln1w, ln1b, lnh);

    // ffn1: gelu(ln @ Wf1^T + bf1) -> fp16
    ga.A[0] = lnh; ga.B[0] = hWf1; ga.C[0] = f1h;
    tgemm<1,1,4><<<dim3(2*HR_DIM/128, 16, 1), 256>>>(ga, bf1, nullptr, 2*HR_DIM, HR_DIM, t0);

    // ffn2 + residual -> fp16
    ga.A[0] = f1h; ga.B[0] = hWf2; ga.C[0] = hidh;
    tgemm<2,1,4><<<dim3(E_DIM/128, 16, 1), 256>>>(ga, bf2, x, E_DIM, 2*HR_DIM, t0);

    // silu projections -> fp16
    ga.A[0] = hidh; ga.A[1] = hidh;
    ga.B[0] = hWqi1; ga.B[1] = hWki1;
    ga.C[0] = aqh;  ga.C[1] = akh;
    tgemm<3,1,4><<<dim3(HR_DIM/128, 16, 2), 256>>>(ga, nullptr, nullptr, HR_DIM, E_DIM, t0);

    // importance projections with fused rope+permute into output
    ga.A[0] = aqh; ga.A[1] = akh;
    ga.B[0] = hWqi2; ga.B[1] = hWki2;
    ga.C[0] = out;  ga.C[1] = out + (size_t)NLAY*NH*L_SEQ*DD;
    tgemm<4,0,4><<<dim3(OUT_FEAT/128, 16, 2), 256>>>(ga, nullptr, nullptr, OUT_FEAT, HR_DIM, t8);
}

// round 15
// speedup vs baseline: 1.0518x; 1.0063x over previous
#include <cuda_runtime.h>
#include <cuda_fp16.h>
#include <math.h>
#include <stdint.h>

// ------------------------- problem dimensions -------------------------
#define L_SEQ   2048
#define E_DIM   4096
#define HR_DIM  1024
#define NH      32
#define D_ATT   32
#define NLAY    32
#define DD      16
#define OUT_FEAT (NLAY*NH*DD)   // 16384

// ------------------------- scratch (static device mem) ----------------
__device__ float g_attn[(size_t)L_SEQ*HR_DIM];
__device__ __half g_xh   [(size_t)L_SEQ*E_DIM];
__device__ __half g_hWi  [(size_t)HR_DIM*E_DIM];
__device__ __half g_hWq  [(size_t)HR_DIM*HR_DIM];
__device__ __half g_hWk  [(size_t)HR_DIM*HR_DIM];
__device__ __half g_hWv  [(size_t)HR_DIM*HR_DIM];
__device__ __half g_hWf1 [(size_t)2*HR_DIM*HR_DIM];
__device__ __half g_hWf2 [(size_t)E_DIM*2*HR_DIM];
__device__ __half g_hWqi1[(size_t)HR_DIM*E_DIM];
__device__ __half g_hWki1[(size_t)HR_DIM*E_DIM];
__device__ __half g_hWqi2[(size_t)OUT_FEAT*HR_DIM];
__device__ __half g_hWki2[(size_t)OUT_FEAT*HR_DIM];
__device__ __half g_hrh  [(size_t)L_SEQ*HR_DIM];
__device__ __half g_qh   [(size_t)L_SEQ*HR_DIM];
__device__ __half g_kh   [(size_t)L_SEQ*HR_DIM];
__device__ __half g_vh   [(size_t)L_SEQ*HR_DIM];
__device__ __half g_lnh  [(size_t)L_SEQ*HR_DIM];
__device__ __half g_f1h  [(size_t)L_SEQ*2*HR_DIM];
__device__ __half g_hidh [(size_t)L_SEQ*E_DIM];
__device__ __half g_aqh  [(size_t)L_SEQ*HR_DIM];
__device__ __half g_akh  [(size_t)L_SEQ*HR_DIM];

struct F16 { float f[16]; };
struct GArgs { const __half* A[3]; const __half* B[3]; void* C[3]; };
struct CvtArgs {
    const float4* src[11];
    uint2* dst[11];
    unsigned off[12];   // cumulative float4 counts
};

// ------------------------- helpers ------------------------------------
__device__ __forceinline__ float gelu_f(float x) {
    return 0.5f * x * (1.0f + erff(x * 0.7071067811865476f));
}
__device__ __forceinline__ float silu_f(float x) {
    return x / (1.0f + expf(-x));
}
__device__ __forceinline__ void mma16816(float c[4], const uint32_t a[4], const uint32_t b[2]) {
    asm volatile(
        "mma.sync.aligned.m16n8k16.row.col.f32.f16.f16.f32 "
        "{%0,%1,%2,%3}, {%4,%5,%6,%7}, {%8,%9}, {%0,%1,%2,%3};"
        : "+f"(c[0]), "+f"(c[1]), "+f"(c[2]), "+f"(c[3])
        : "r"(a[0]), "r"(a[1]), "r"(a[2]), "r"(a[3]), "r"(b[0]), "r"(b[1]));
}
__device__ __forceinline__ void cpa16(uint32_t saddr, const __half* g) {
    asm volatile("cp.async.cg.shared.global [%0], [%1], 16;\n" :: "r"(saddr), "l"(g));
}
#define CP_COMMIT() asm volatile("cp.async.commit_group;\n" ::: "memory")
#define CP_WAIT(n)  asm volatile("cp.async.wait_group %0;\n" :: "n"(n) : "memory")
__device__ __forceinline__ void ldsm4(uint32_t& r0, uint32_t& r1, uint32_t& r2, uint32_t& r3,
                                      uint32_t addr) {
    asm volatile("ldmatrix.sync.aligned.m8n8.x4.shared.b16 {%0,%1,%2,%3}, [%4];"
                 : "=r"(r0), "=r"(r1), "=r"(r2), "=r"(r3) : "r"(addr));
}
__device__ __forceinline__ void ldsm4t(uint32_t& r0, uint32_t& r1, uint32_t& r2, uint32_t& r3,
                                       uint32_t addr) {
    asm volatile("ldmatrix.sync.aligned.m8n8.x4.trans.shared.b16 {%0,%1,%2,%3}, [%4];"
                 : "=r"(r0), "=r"(r1), "=r"(r2), "=r"(r3) : "r"(addr));
}
__device__ __forceinline__ uint32_t packh2(float a, float b) {
    __half2 h = __floats2half2_rn(a, b);
    return *reinterpret_cast<uint32_t*>(&h);
}

// ------------------ batched convert: dst[s] = half(src[s]) ------------
__global__ __launch_bounds__(256)
void cvt_all(CvtArgs a)
{
    unsigned gid = blockIdx.x * 256u + threadIdx.x;
    if (gid >= a.off[11]) return;
    int s = 0;
#pragma unroll
    for (int i = 1; i < 11; i++) s += (gid >= a.off[i]) ? 1 : 0;
    unsigned idx = gid - a.off[s];
    float4 v = a.src[s][idx];
    uint2 o;
    o.x = packh2(v.x, v.y);
    o.y = packh2(v.z, v.w);
    a.dst[s][idx] = o;
}

// ---------------- FP16 GEMM: C[2048,N] = A[2048,K] * B[N,K]^T ---------
// CTA tile (MI*32)x128x32, 8 warps (2m x 4n), warp tile (MI*16)x32.
// MI=4 everywhere (round-12 proven config). 2-stage cp.async.
// EPI: 0 none, 1 gelu(acc+bias), 2 acc+bias+resid, 3 silu(acc),
//      4 rope+permute into output (qi/ki), 5 qkv rope (z<2) fp16 out
// OUTH: 1 -> fp16 C, 0 -> fp32 C
template<int EPI, int OUTH, int MI>
__global__ __launch_bounds__(256, 2)
void tgemm(GArgs ga, const float* __restrict__ bias,
           const float* __restrict__ resid, int N, int K, F16 ft)
{
    constexpr int MROWS = MI * 32;
    constexpr int AIT = MI / 2;
    __shared__ __align__(16) __half sA[2][MROWS*32];
    __shared__ __align__(16) __half sB[2][128*32];

    const __half* __restrict__ A = ga.A[blockIdx.z];
    const __half* __restrict__ B = ga.B[blockIdx.z];

    const int tid = threadIdx.x, wid = tid >> 5, lane = tid & 31;
    const int g = lane >> 2, tig = lane & 3;
    const int wm = (wid & 1) * (MI * 16);
    const int wn = (wid >> 1) * 32;
    const int bm = blockIdx.y * MROWS, bn = blockIdx.x * 128;

    uint32_t sA_u[2], sB_u[2];
    sA_u[0] = (uint32_t)__cvta_generic_to_shared(&sA[0][0]);
    sA_u[1] = (uint32_t)__cvta_generic_to_shared(&sA[1][0]);
    sB_u[0] = (uint32_t)__cvta_generic_to_shared(&sB[0][0]);
    sB_u[1] = (uint32_t)__cvta_generic_to_shared(&sB[1][0]);

    uint32_t aoff[AIT], boff[2];
    const __half* aptr[AIT];
    const __half* bptr[2];
#pragma unroll
    for (int i = 0; i < AIT; i++) {
        int id = tid + i * 256;
        int r = id >> 2, c = id & 3;
        aoff[i] = (uint32_t)(r * 64 + ((c ^ ((r >> 1) & 3)) << 4));
        aptr[i] = A + (size_t)(bm + r) * K + c * 8;
    }
#pragma unroll
    for (int i = 0; i < 2; i++) {
        int id = tid + i * 256;
        int r = id >> 2, c = id & 3;
        boff[i] = (uint32_t)(r * 64 + ((c ^ ((r >> 1) & 3)) << 4));
        bptr[i] = B + (size_t)(bn + r) * K + c * 8;
    }

    const int cAbit = lane >> 4;
    uint32_t aRowByte[MI]; int aMask[MI];
#pragma unroll
    for (int mi = 0; mi < MI; mi++) {
        int r = wm + mi * 16 + (lane & 15);
        aRowByte[mi] = (uint32_t)(r * 64);
        aMask[mi] = (r >> 1) & 3;
    }
    const int cBbit = (lane >> 3) & 1;
    uint32_t bRowByte[2]; int bMask[2];
#pragma unroll
    for (int p = 0; p < 2; p++) {
        int r = wn + p * 16 + ((lane >> 4) << 3) + (lane & 7);
        bRowByte[p] = (uint32_t)(r * 64);
        bMask[p] = (r >> 1) & 3;
    }

    float acc[MI][4][4];
#pragma unroll
    for (int mi = 0; mi < MI; mi++)
#pragma unroll
        for (int ni = 0; ni < 4; ni++)
#pragma unroll
            for (int c = 0; c < 4; c++) acc[mi][ni][c] = 0.0f;

#pragma unroll
    for (int i = 0; i < AIT; i++) { cpa16(sA_u[0] + aoff[i], aptr[i]); }
#pragma unroll
    for (int i = 0; i < 2; i++) { cpa16(sB_u[0] + boff[i], bptr[i]); }
    CP_COMMIT();
#pragma unroll
    for (int i = 0; i < AIT; i++) aptr[i] += 32;
#pragma unroll
    for (int i = 0; i < 2; i++) bptr[i] += 32;

    const int T = K >> 5;
    for (int t = 0; t < T; t++) {
        const int cur = t & 1, nxt = cur ^ 1;
        if (t + 1 < T) {
#pragma unroll
            for (int i = 0; i < AIT; i++) { cpa16(sA_u[nxt] + aoff[i], aptr[i]); }
#pragma unroll
            for (int i = 0; i < 2; i++) { cpa16(sB_u[nxt] + boff[i], bptr[i]); }
            CP_COMMIT();
#pragma unroll
            for (int i = 0; i < AIT; i++) aptr[i] += 32;
#pragma unroll
            for (int i = 0; i < 2; i++) bptr[i] += 32;
            CP_WAIT(1);
        } else {
            CP_WAIT(0);
        }
        __syncthreads();

        const uint32_t sAc = sA_u[cur], sBc = sB_u[cur];
#pragma unroll
        for (int kk = 0; kk < 2; kk++) {
            uint32_t af[MI][4], bf[4][2];
#pragma unroll
            for (int mi = 0; mi < MI; mi++)
                ldsm4(af[mi][0], af[mi][1], af[mi][2], af[mi][3],
                      sAc + aRowByte[mi] + (uint32_t)(((2*kk + cAbit) ^ aMask[mi]) << 4));
#pragma unroll
            for (int p = 0; p < 2; p++)
                ldsm4(bf[p*2][0], bf[p*2][1], bf[p*2+1][0], bf[p*2+1][1],
                      sBc + bRowByte[p] + (uint32_t)(((2*kk + cBbit) ^ bMask[p]) << 4));
#pragma unroll
            for (int mi = 0; mi < MI; mi++)
#pragma unroll
                for (int ni = 0; ni < 4; ni++)
                    mma16816(acc[mi][ni], af[mi], bf[ni]);
        }
        __syncthreads();
    }

    // ---------------- epilogue ----------------
    if (EPI == 4) {
        float* __restrict__ Cf = (float*)ga.C[blockIdx.z];
#pragma unroll
        for (int mi = 0; mi < MI; mi++) {
#pragma unroll
            for (int j = 0; j < 2; j++) {
                int nb = bn + wn + j * 16;
                int h  = (nb >> 4) & 31;
                int nl = nb >> 9;
                size_t ob0 = ((size_t)(nl * NH + h)) * L_SEQ;
                int i0 = tig * 2;
#pragma unroll
                for (int hf = 0; hf < 2; hf++) {
                    int l = bm + wm + mi * 16 + g + hf * 8;
                    size_t ob = (ob0 + l) * DD + i0;
                    float x1a = acc[mi][j*2  ][hf*2+0];
                    float x1b = acc[mi][j*2  ][hf*2+1];
                    float x2a = acc[mi][j*2+1][hf*2+0];
                    float x2b = acc[mi][j*2+1][hf*2+1];
                    float a0 = (float)l * ft.f[i0];
                    float a1 = (float)l * ft.f[i0+1];
                    float c0 = cosf(a0), s0 = sinf(a0);
                    float c1 = cosf(a1), s1 = sinf(a1);
                    *reinterpret_cast<float2*>(Cf + ob) =
                        make_float2(x1a*c0 - x2a*s0, x1b*c1 - x2b*s1);
                    *reinterpret_cast<float2*>(Cf + ob + 8) =
                        make_float2(x2a*c0 + x1a*s0, x2b*c1 + x1b*s1);
                }
            }
        }
        return;
    }
    if (EPI == 5) {
        __half* __restrict__ Ch = (__half*)ga.C[blockIdx.z];
        const bool dorope = (blockIdx.z < 2);
        const float sc = (blockIdx.z == 0) ? 0.17677669529663687f : 1.0f;
#pragma unroll
        for (int mi = 0; mi < MI; mi++) {
#pragma unroll
            for (int hf = 0; hf < 2; hf++) {
                int l = bm + wm + mi * 16 + g + hf * 8;
                size_t rowo = (size_t)l * N;
#pragma unroll
                for (int ni = 0; ni < 2; ni++) {
                    int i0 = ni * 8 + tig * 2;
                    int n0 = bn + wn + ni * 8 + tig * 2;
                    float x1a = acc[mi][ni  ][hf*2+0] * sc;
                    float x1b = acc[mi][ni  ][hf*2+1] * sc;
                    float x2a = acc[mi][ni+2][hf*2+0] * sc;
                    float x2b = acc[mi][ni+2][hf*2+1] * sc;
                    float y1a, y1b, y2a, y2b;
                    if (dorope) {
                        float a0 = (float)l * ft.f[i0];
                        float a1 = (float)l * ft.f[i0+1];
                        float c0 = cosf(a0), s0 = sinf(a0);
                        float c1 = cosf(a1), s1 = sinf(a1);
                        y1a = x1a*c0 - x2a*s0; y1b = x1b*c1 - x2b*s1;
                        y2a = x2a*c0 + x1a*s0; y2b = x2b*c1 + x1b*s1;
                    } else {
                        y1a = x1a; y1b = x1b; y2a = x2a; y2b = x2b;
                    }
                    *reinterpret_cast<uint32_t*>(Ch + rowo + n0)      = packh2(y1a, y1b);
                    *reinterpret_cast<uint32_t*>(Ch + rowo + n0 + 16) = packh2(y2a, y2b);
                }
            }
        }
        return;
    }

#pragma unroll
    for (int mi = 0; mi < MI; mi++) {
#pragma unroll
        for (int ni = 0; ni < 4; ni++) {
            int m0 = bm + wm + mi * 16 + g;
            int n0 = bn + wn + ni * 8 + tig * 2;
#pragma unroll
            for (int hf = 0; hf < 2; hf++) {
                int m = m0 + hf * 8;
                size_t off = (size_t)m * N + n0;
                float v0 = acc[mi][ni][hf * 2 + 0];
                float v1 = acc[mi][ni][hf * 2 + 1];
                if (EPI == 1) {
                    v0 = gelu_f(v0 + bias[n0]); v1 = gelu_f(v1 + bias[n0 + 1]);
                } else if (EPI == 2) {
                    v0 = v0 + bias[n0] + resid[off];
                    v1 = v1 + bias[n0 + 1] + resid[off + 1];
                } else if (EPI == 3) {
                    v0 = silu_f(v0); v1 = silu_f(v1);
                }
                if (OUTH) {
                    *reinterpret_cast<uint32_t*>((__half*)ga.C[blockIdx.z] + off) = packh2(v0, v1);
                } else {
                    *reinterpret_cast<float2*>((float*)ga.C[blockIdx.z] + off) =
                        make_float2(v0, v1);
                }
            }
        }
    }
}

// ---------------- tensor-core causal flash attention ------------------
// block = (128 queries, 1 head), 8 warps x 16 rows each (parallel);
// K/V tiles of 64 keys shared by all 8 warps.
__global__ __launch_bounds__(256)
void attn_mma(const __half* __restrict__ Q, const __half* __restrict__ K,
              const __half* __restrict__ V, float* __restrict__ O)
{
    __shared__ __align__(16) __half sQ[128*32];
    __shared__ __align__(16) __half sK[64*32];
    __shared__ __align__(16) __half sV[64*32];
    const int h = blockIdx.y;
    const int q0 = blockIdx.x * 128;
    const int tid = threadIdx.x, w = tid >> 5, lane = tid & 31;
    const int g = lane >> 2, tig = lane & 3;

    const uint32_t uQ = (uint32_t)__cvta_generic_to_shared(sQ);
    const uint32_t uK = (uint32_t)__cvta_generic_to_shared(sK);
    const uint32_t uV = (uint32_t)__cvta_generic_to_shared(sV);

    // load Q tile (128 rows x 32 halves, swizzled 16B chunks)
#pragma unroll
    for (int i = 0; i < 2; i++) {
        int id = tid + i * 256;
        int r = id >> 2, c = id & 3;
        *reinterpret_cast<uint4*>(sQ + r * 32 + ((c ^ ((r >> 1) & 3)) << 3)) =
            *reinterpret_cast<const uint4*>(Q + (size_t)(q0 + r) * HR_DIM + h * 32 + c * 8);
    }

    // fragment addressing (per-warp 16-row slice)
    const int cAbit = lane >> 4;
    const int aR = w * 16 + (lane & 15);
    const uint32_t aRowByte = (uint32_t)(aR * 64);
    const int aMask = (aR >> 1) & 3;
    const int cBbit = (lane >> 3) & 1;
    uint32_t bRowByte[4]; int bMask[4];
#pragma unroll
    for (int p = 0; p < 4; p++) {
        int r = p * 16 + ((lane >> 4) << 3) + (lane & 7);
        bRowByte[p] = (uint32_t)(r * 64);
        bMask[p] = (r >> 1) & 3;
    }
    const int vR0 = ((lane >> 3) & 1) * 8 + (lane & 7);
    const uint32_t vRowByte = (uint32_t)(vR0 * 64);
    const int vMask = (vR0 >> 1) & 3;
    const int vCbit = lane >> 4;

    float m0 = -INFINITY, m1 = -INFINITY, l0 = 0.0f, l1 = 0.0f;
    float Of[4][4];
#pragma unroll
    for (int nb = 0; nb < 4; nb++)
#pragma unroll
        for (int c = 0; c < 4; c++) Of[nb][c] = 0.0f;

    const int dtile = blockIdx.x * 2 + (w >> 2);   // this warp's diagonal K-tile
    const int nt = blockIdx.x * 2 + 2;             // K/V tiles this block touches
    for (int tix = 0; tix < nt; tix++) {
        const int j0 = tix * 64;
        // load K,V tiles: 64 rows x 4 chunks = 256 threads exactly
        {
            int r = tid >> 2, c = tid & 3;
            uint32_t so = r * 32 + ((c ^ ((r >> 1) & 3)) << 3);
            size_t go = (size_t)(j0 + r) * HR_DIM + h * 32 + c * 8;
            *reinterpret_cast<uint4*>(sK + so) = *reinterpret_cast<const uint4*>(K + go);
            *reinterpret_cast<uint4*>(sV + so) = *reinterpret_cast<const uint4*>(V + go);
        }
        __syncthreads();

        if (tix <= dtile) {
            // S = Q @ K^T  (16 rows x 64 keys per warp)
            float Sf[8][4];
#pragma unroll
            for (int nb = 0; nb < 8; nb++)
#pragma unroll
                for (int c = 0; c < 4; c++) Sf[nb][c] = 0.0f;
#pragma unroll
            for (int kk = 0; kk < 2; kk++) {
                uint32_t af[4], bf[8][2];
                ldsm4(af[0], af[1], af[2], af[3],
                      uQ + aRowByte + (uint32_t)(((2*kk + cAbit) ^ aMask) << 4));
#pragma unroll
                for (int p = 0; p < 4; p++)
                    ldsm4(bf[p*2][0], bf[p*2][1], bf[p*2+1][0], bf[p*2+1][1],
                          uK + bRowByte[p] + (uint32_t)(((2*kk + cBbit) ^ bMask[p]) << 4));
#pragma unroll
                for (int nb = 0; nb < 8; nb++)
                    mma16816(Sf[nb], af, bf[nb]);
            }

            // causal mask on this warp's diagonal tile
            if (tix == dtile) {
                const int lr0 = q0 + w * 16 + g;
#pragma unroll
                for (int nb = 0; nb < 8; nb++) {
                    int j = j0 + nb * 8 + tig * 2;
                    if (j     > lr0    ) Sf[nb][0] = -1e30f;
                    if (j + 1 > lr0    ) Sf[nb][1] = -1e30f;
                    if (j     > lr0 + 8) Sf[nb][2] = -1e30f;
                    if (j + 1 > lr0 + 8) Sf[nb][3] = -1e30f;
                }
            }

            // online softmax (rows g and g+8)
            float mx0 = -INFINITY, mx1 = -INFINITY;
#pragma unroll
            for (int nb = 0; nb < 8; nb++) {
                mx0 = fmaxf(mx0, fmaxf(Sf[nb][0], Sf[nb][1]));
                mx1 = fmaxf(mx1, fmaxf(Sf[nb][2], Sf[nb][3]));
            }
            mx0 = fmaxf(mx0, __shfl_xor_sync(0xffffffffu, mx0, 1));
            mx0 = fmaxf(mx0, __shfl_xor_sync(0xffffffffu, mx0, 2));
            mx1 = fmaxf(mx1, __shfl_xor_sync(0xffffffffu, mx1, 1));
            mx1 = fmaxf(mx1, __shfl_xor_sync(0xffffffffu, mx1, 2));
            float mn0 = fmaxf(m0, mx0), mn1 = fmaxf(m1, mx1);
            float al0 = __expf(m0 - mn0), al1 = __expf(m1 - mn1);
            float ps0 = 0.0f, ps1 = 0.0f;
#pragma unroll
            for (int nb = 0; nb < 8; nb++) {
                Sf[nb][0] = __expf(Sf[nb][0] - mn0);
                Sf[nb][1] = __expf(Sf[nb][1] - mn0);
                Sf[nb][2] = __expf(Sf[nb][2] - mn1);
                Sf[nb][3] = __expf(Sf[nb][3] - mn1);
                ps0 += Sf[nb][0] + Sf[nb][1];
                ps1 += Sf[nb][2] + Sf[nb][3];
            }
            ps0 += __shfl_xor_sync(0xffffffffu, ps0, 1);
            ps0 += __shfl_xor_sync(0xffffffffu, ps0, 2);
            ps1 += __shfl_xor_sync(0xffffffffu, ps1, 1);
            ps1 += __shfl_xor_sync(0xffffffffu, ps1, 2);
            l0 = l0 * al0 + ps0;
            l1 = l1 * al1 + ps1;
            m0 = mn0; m1 = mn1;
#pragma unroll
            for (int nb = 0; nb < 4; nb++) {
                Of[nb][0] *= al0; Of[nb][1] *= al0;
                Of[nb][2] *= al1; Of[nb][3] *= al1;
            }

            // P (fp16) @ V
#pragma unroll
            for (int kk = 0; kk < 4; kk++) {
                uint32_t pf[4];
                pf[0] = packh2(Sf[2*kk  ][0], Sf[2*kk  ][1]);
                pf[1] = packh2(Sf[2*kk  ][2], Sf[2*kk  ][3]);
                pf[2] = packh2(Sf[2*kk+1][0], Sf[2*kk+1][1]);
                pf[3] = packh2(Sf[2*kk+1][2], Sf[2*kk+1][3]);
#pragma unroll
                for (int p = 0; p < 2; p++) {
                    uint32_t v0, v1, v2, v3;
                    int dchunk = 2 * p + vCbit;
                    ldsm4t(v0, v1, v2, v3,
                           uV + vRowByte + (uint32_t)(kk * 16 * 64)
                              + (uint32_t)((dchunk ^ vMask) << 4));
                    uint32_t b0[2] = {v0, v1};
                    uint32_t b1[2] = {v2, v3};
                    mma16816(Of[p*2],   pf, b0);
                    mma16816(Of[p*2+1], pf, b1);
                }
            }
        }
        __syncthreads();
    }

    // write O = Of / l
    float inv0 = 1.0f / l0, inv1 = 1.0f / l1;
    const int lr = q0 + w * 16 + g;
#pragma unroll
    for (int nb = 0; nb < 4; nb++) {
        int d0 = nb * 8 + tig * 2;
        *reinterpret_cast<float2*>(O + (size_t)lr * HR_DIM + h * 32 + d0) =
            make_float2(Of[nb][0] * inv0, Of[nb][1] * inv0);
        *reinterpret_cast<float2*>(O + (size_t)(lr + 8) * HR_DIM + h * 32 + d0) =
            make_float2(Of[nb][2] * inv1, Of[nb][3] * inv1);
    }
}

// ------------------------- LayerNorm (rows of 1024, fp16 out) ---------
__global__ __launch_bounds__(256)
void layernorm_k(const float* __restrict__ in, const float* __restrict__ w,
                 const float* __restrict__ b, __half* __restrict__ out)
{
    __shared__ float red[8];
    const int row = blockIdx.x;
    const int tid = threadIdx.x;
    const int lane = tid & 31, wid = tid >> 5;
    float4 v = reinterpret_cast<const float4*>(in + (size_t)row * HR_DIM)[tid];

    float s = v.x + v.y + v.z + v.w;
#pragma unroll
    for (int o = 16; o; o >>= 1) s += __shfl_xor_sync(0xffffffffu, s, o);
    if (lane == 0) red[wid] = s;
    __syncthreads();
    float tot = red[0]+red[1]+red[2]+red[3]+red[4]+red[5]+red[6]+red[7];
    float mu = tot * (1.0f / HR_DIM);

    float dx0 = v.x - mu, dx1 = v.y - mu, dx2 = v.z - mu, dx3 = v.w - mu;
    float sq = dx0*dx0 + dx1*dx1 + dx2*dx2 + dx3*dx3;
#pragma unroll
    for (int o = 16; o; o >>= 1) sq += __shfl_xor_sync(0xffffffffu, sq, o);
    __syncthreads();
    if (lane == 0) red[wid] = sq;
    __syncthreads();
    float var = (red[0]+red[1]+red[2]+red[3]+red[4]+red[5]+red[6]+red[7]) * (1.0f / HR_DIM);
    float rstd = rsqrtf(var + 1e-5f);

    float4 wv = reinterpret_cast<const float4*>(w)[tid];
    float4 bv = reinterpret_cast<const float4*>(b)[tid];
    uint2 o;
    o.x = packh2(dx0 * rstd * wv.x + bv.x, dx1 * rstd * wv.y + bv.y);
    o.y = packh2(dx2 * rstd * wv.z + bv.z, dx3 * rstd * wv.w + bv.w);
    reinterpret_cast<uint2*>(out + (size_t)row * HR_DIM)[tid] = o;
}

// ------------------------- launcher -----------------------------------
extern "C" void kernel_launch(void* const* d_in, const int* in_sizes, int n_in,
                              void* d_out, int out_size)
{
    const float* x    = (const float*)d_in[0];
    const float* Wi   = (const float*)d_in[1];
    const float* Wq   = (const float*)d_in[2];
    const float* Wk   = (const float*)d_in[3];
    const float* Wv   = (const float*)d_in[4];
    const float* ln1w = (const float*)d_in[5];
    const float* ln1b = (const float*)d_in[6];
    const float* Wf1  = (const float*)d_in[7];
    const float* bf1  = (const float*)d_in[8];
    const float* Wf2  = (const float*)d_in[9];
    const float* bf2  = (const float*)d_in[10];
    const float* Wqi1 = (const float*)d_in[11];
    const float* Wqi2 = (const float*)d_in[12];
    const float* Wki1 = (const float*)d_in[13];
    const float* Wki2 = (const float*)d_in[14];
    float* out = (float*)d_out;

    float *attn;
    __half *xh,*hWi,*hWq,*hWk,*hWv,*hWf1,*hWf2,*hWqi1,*hWki1,*hWqi2,*hWki2;
    __half *hrh,*qh,*kh,*vh,*lnh,*f1h,*hidh,*aqh,*akh;
    cudaGetSymbolAddress((void**)&attn, g_attn);
    cudaGetSymbolAddress((void**)&xh,    g_xh);
    cudaGetSymbolAddress((void**)&hWi,   g_hWi);
    cudaGetSymbolAddress((void**)&hWq,   g_hWq);
    cudaGetSymbolAddress((void**)&hWk,   g_hWk);
    cudaGetSymbolAddress((void**)&hWv,   g_hWv);
    cudaGetSymbolAddress((void**)&hWf1,  g_hWf1);
    cudaGetSymbolAddress((void**)&hWf2,  g_hWf2);
    cudaGetSymbolAddress((void**)&hWqi1, g_hWqi1);
    cudaGetSymbolAddress((void**)&hWki1, g_hWki1);
    cudaGetSymbolAddress((void**)&hWqi2, g_hWqi2);
    cudaGetSymbolAddress((void**)&hWki2, g_hWki2);
    cudaGetSymbolAddress((void**)&hrh,   g_hrh);
    cudaGetSymbolAddress((void**)&qh,    g_qh);
    cudaGetSymbolAddress((void**)&kh,    g_kh);
    cudaGetSymbolAddress((void**)&vh,    g_vh);
    cudaGetSymbolAddress((void**)&lnh,   g_lnh);
    cudaGetSymbolAddress((void**)&f1h,   g_f1h);
    cudaGetSymbolAddress((void**)&hidh,  g_hidh);
    cudaGetSymbolAddress((void**)&aqh,   g_aqh);
    cudaGetSymbolAddress((void**)&akh,   g_akh);

    F16 t16; for (int i = 0; i < 16; i++) t16.f[i] = (float)(1.0 / pow(10000.0, (double)i / 16.0));
    F16 t8 = {}; for (int i = 0; i < 8; i++) t8.f[i] = (float)(1.0 / pow(10000.0, (double)i / 8.0));
    F16 t0 = {};

    // one batched fp32->fp16 convert over all 11 operands
    {
        CvtArgs ca;
        const float* srcs[11] = {x, Wi, Wq, Wk, Wv, Wf1, Wf2, Wqi1, Wki1, Wqi2, Wki2};
        __half* dsts[11] = {xh, hWi, hWq, hWk, hWv, hWf1, hWf2, hWqi1, hWki1, hWqi2, hWki2};
        size_t cnts[11] = {
            (size_t)L_SEQ*E_DIM, (size_t)HR_DIM*E_DIM,
            (size_t)HR_DIM*HR_DIM, (size_t)HR_DIM*HR_DIM, (size_t)HR_DIM*HR_DIM,
            (size_t)2*HR_DIM*HR_DIM, (size_t)E_DIM*2*HR_DIM,
            (size_t)HR_DIM*E_DIM, (size_t)HR_DIM*E_DIM,
            (size_t)OUT_FEAT*HR_DIM, (size_t)OUT_FEAT*HR_DIM
        };
        unsigned acc = 0;
        for (int i = 0; i < 11; i++) {
            ca.src[i] = (const float4*)srcs[i];
            ca.dst[i] = (uint2*)dsts[i];
            ca.off[i] = acc;
            acc += (unsigned)(cnts[i] / 4);
        }
        ca.off[11] = acc;
        cvt_all<<<(acc + 255) / 256, 256>>>(ca);
    }

    GArgs ga;

    // hr = x @ Wi^T  (fp16 out)
    ga.A[0] = xh; ga.B[0] = hWi; ga.C[0] = hrh;
    tgemm<0,1,4><<<dim3(HR_DIM/128, 16, 1), 256>>>(ga, nullptr, nullptr, HR_DIM, E_DIM, t0);

    // q, k, v with fused rope (q scaled), fp16 out
    ga.A[0] = hrh; ga.A[1] = hrh; ga.A[2] = hrh;
    ga.B[0] = hWq; ga.B[1] = hWk; ga.B[2] = hWv;
    ga.C[0] = qh;  ga.C[1] = kh;  ga.C[2] = vh;
    tgemm<5,1,4><<<dim3(HR_DIM/128, 16, 3), 256>>>(ga, nullptr, nullptr, HR_DIM, HR_DIM, t16);

    attn_mma<<<dim3(L_SEQ/128, NH), 256>>>(qh, kh, vh, attn);
    layernorm_k<<<L_SEQ, 256>>>(attn, ln1w, ln1b, lnh);

    // ffn1: gelu(ln @ Wf1^T + bf1) -> fp16
    ga.A[0] = lnh; ga.B[0] = hWf1; ga.C[0] = f1h;
    tgemm<1,1,4><<<dim3(2*HR_DIM/128, 16, 1), 256>>>(ga, bf1, nullptr, 2*HR_DIM, HR_DIM, t0);

    // ffn2 + residual -> fp16
    ga.A[0] = f1h; ga.B[0] = hWf2; ga.C[0] = hidh;
    tgemm<2,1,4><<<dim3(E_DIM/128, 16, 1), 256>>>(ga, bf2, x, E_DIM, 2*HR_DIM, t0);

    // silu projections -> fp16
    ga.A[0] = hidh; ga.A[1] = hidh;
    ga.B[0] = hWqi1; ga.B[1] = hWki1;
    ga.C[0] = aqh;  ga.C[1] = akh;
    tgemm<3,1,4><<<dim3(HR_DIM/128, 16, 2), 256>>>(ga, nullptr, nullptr, HR_DIM, E_DIM, t0);

    // importance projections with fused rope+permute into output
    ga.A[0] = aqh; ga.A[1] = akh;
    ga.B[0] = hWqi2; ga.B[1] = hWki2;
    ga.C[0] = out;  ga.C[1] = out + (size_t)NLAY*NH*L_SEQ*DD;
    tgemm<4,0,4><<<dim3(OUT_FEAT/128, 16, 2), 256>>>(ga, nullptr, nullptr, OUT_FEAT, HR_DIM, t8);
}